// round 5
// baseline (speedup 1.0000x reference)
#include <cuda_runtime.h>
#include <math.h>
#include <stdint.h>

#define NN 32768
#define EE 262144
#define DD 256
#define HH 4
#define GG 32
#define BN_EPS 1e-5f

// ------------------------- scratch (device globals) -------------------------
__device__ float g_h[NN * DD];
__device__ float g_q[NN * DD];
__device__ float g_k[NN * DD];
__device__ float g_v[NN * DD];
__device__ float g_xr[NN * DD];
__device__ float g_msg[NN * DD];      // UNNORMALIZED attention aggregate: sum ex*(v+e)
__device__ float g_den[NN * HH];      // softmax denominators per dst node/head
__device__ float g_colstats[2 * DD];  // [0..255] colsum, [256..511] colsumsq
__device__ float g_gate[NN];          // exp(gate) per node
__device__ float g_gden[GG];          // per-graph softmax denom
__device__ float g_hG[GG * DD];       // pooled per-graph embedding

// ------------------------- zero kernels -------------------------
__global__ void zero_layer_kernel() {
    int i = blockIdx.x * blockDim.x + threadIdx.x;
    if (i < NN * DD) g_msg[i] = 0.f;
    if (i < NN * HH) g_den[i] = 0.f;
    if (i < 2 * DD) g_colstats[i] = 0.f;
}

__global__ void zero_readout_kernel() {
    int i = blockIdx.x * blockDim.x + threadIdx.x;
    if (i < GG * DD) g_hG[i] = 0.f;
    if (i < GG) g_gden[i] = 0.f;
}

// ------------------------- encoder: h = x @ enc_W + enc_b -------------------------
__global__ void encoder_kernel(const float* __restrict__ x,
                               const float* __restrict__ W,
                               const float* __restrict__ b) {
    int i = blockIdx.x * blockDim.x + threadIdx.x;
    if (i >= NN * DD) return;
    int n = i >> 8, d = i & 255;
    g_h[i] = x[n * 2] * W[d] + x[n * 2 + 1] * W[DD + d] + b[d];
}

// ------------------------- TF32x3 tensor-core GEMM (fp32-accurate) -------------------------
// C = g_h[32768x256] @ B[256x256] + bias via mma.sync m16n8k8 tf32, hi/lo split:
//   C ~= Ahi*Bhi + Ahi*Blo + Alo*Bhi   (Alo*Blo ~ 2^-24, dropped)
#define SA 20    // A smem stride (floats): conflict-free, float4-aligned slots
#define SB 136   // B smem stride (floats): conflict-free

__device__ __forceinline__ uint32_t f2tf32(float f) {
    uint32_t r;
    asm("cvt.rna.tf32.f32 %0, %1;" : "=r"(r) : "f"(f));
    return r;
}

__device__ __forceinline__ void cp16(uint32_t s, const void* g) {
    asm volatile("cp.async.ca.shared.global [%0], [%1], 16;" :: "r"(s), "l"(g));
}

__device__ __forceinline__ void mma8(float* c, const uint32_t* a, const uint32_t* b) {
    asm volatile(
        "mma.sync.aligned.m16n8k8.row.col.f32.tf32.tf32.f32 "
        "{%0,%1,%2,%3}, {%4,%5,%6,%7}, {%8,%9}, {%0,%1,%2,%3};"
        : "+f"(c[0]), "+f"(c[1]), "+f"(c[2]), "+f"(c[3])
        : "r"(a[0]), "r"(a[1]), "r"(a[2]), "r"(a[3]), "r"(b[0]), "r"(b[1]));
}

__device__ __forceinline__ void split_tf32(float x, uint32_t& hi, uint32_t& lo) {
    hi = f2tf32(x);
    lo = f2tf32(x - __uint_as_float(hi));
}

__global__ __launch_bounds__(256, 2) void mma_gemm_bias(const float* __restrict__ B,
                                                        const float* __restrict__ bias,
                                                        int outsel) {
    __shared__ float As[2][128 * SA];
    __shared__ float Bs[2][16 * SB];

    float* Cm = (outsel == 0) ? g_q : (outsel == 1) ? g_k : (outsel == 2) ? g_v : g_xr;
    const float* A = g_h;

    int tid = threadIdx.x;
    int warp = tid >> 5, lane = tid & 31;
    int gid = lane >> 2, tig = lane & 3;
    int warp_m = (warp & 1) * 64;
    int warp_n = (warp >> 1) * 32;
    int bm = blockIdx.y * 128, bn = blockIdx.x * 128;

    float acc[4][4][4];
#pragma unroll
    for (int i = 0; i < 4; i++)
#pragma unroll
        for (int j = 0; j < 4; j++)
#pragma unroll
            for (int r = 0; r < 4; r++) acc[i][j][r] = 0.f;

    uint32_t as_base = (uint32_t)__cvta_generic_to_shared(&As[0][0]);
    uint32_t bs_base = (uint32_t)__cvta_generic_to_shared(&Bs[0][0]);

    int a_row = tid >> 2, a_kq = (tid & 3) * 4;
    int b_row = tid >> 5, b_nq = (tid & 31) * 4;

    auto load_tiles = [&](int buf, int k0) {
        cp16(as_base + (uint32_t)(buf * 128 * SA + a_row * SA + a_kq) * 4u,
             &A[(size_t)(bm + a_row) * 256 + k0 + a_kq]);
        cp16(as_base + (uint32_t)(buf * 128 * SA + (a_row + 64) * SA + a_kq) * 4u,
             &A[(size_t)(bm + a_row + 64) * 256 + k0 + a_kq]);
        cp16(bs_base + (uint32_t)(buf * 16 * SB + b_row * SB + b_nq) * 4u,
             &B[(size_t)(k0 + b_row) * 256 + bn + b_nq]);
        cp16(bs_base + (uint32_t)(buf * 16 * SB + (b_row + 8) * SB + b_nq) * 4u,
             &B[(size_t)(k0 + b_row + 8) * 256 + bn + b_nq]);
    };

    load_tiles(0, 0);
    asm volatile("cp.async.commit_group;");

    for (int it = 0; it < 16; it++) {
        int buf = it & 1;
        if (it + 1 < 16) load_tiles(buf ^ 1, (it + 1) * 16);
        asm volatile("cp.async.commit_group;");
        asm volatile("cp.async.wait_group 1;");
        __syncthreads();

        const float* Ab = &As[buf][0];
        const float* Bb = &Bs[buf][0];
#pragma unroll
        for (int ks = 0; ks < 16; ks += 8) {
            uint32_t bhi[4][2], blo[4][2];
#pragma unroll
            for (int fn = 0; fn < 4; fn++) {
                int n = warp_n + fn * 8 + gid;
                split_tf32(Bb[(ks + tig) * SB + n], bhi[fn][0], blo[fn][0]);
                split_tf32(Bb[(ks + tig + 4) * SB + n], bhi[fn][1], blo[fn][1]);
            }
#pragma unroll
            for (int fm = 0; fm < 4; fm++) {
                int m = warp_m + fm * 16 + gid;
                uint32_t ahi[4], alo[4];
                split_tf32(Ab[m * SA + ks + tig], ahi[0], alo[0]);
                split_tf32(Ab[(m + 8) * SA + ks + tig], ahi[1], alo[1]);
                split_tf32(Ab[m * SA + ks + tig + 4], ahi[2], alo[2]);
                split_tf32(Ab[(m + 8) * SA + ks + tig + 4], ahi[3], alo[3]);
#pragma unroll
                for (int fn = 0; fn < 4; fn++) {
                    mma8(acc[fm][fn], ahi, bhi[fn]);
                    mma8(acc[fm][fn], alo, bhi[fn]);
                    mma8(acc[fm][fn], ahi, blo[fn]);
                }
            }
        }
        __syncthreads();
    }

#pragma unroll
    for (int fm = 0; fm < 4; fm++) {
        int row = bm + warp_m + fm * 16 + gid;
#pragma unroll
        for (int fn = 0; fn < 4; fn++) {
            int col = bn + warp_n + fn * 8 + tig * 2;
            float b0 = bias[col], b1 = bias[col + 1];
            float2 o0 = make_float2(acc[fm][fn][0] + b0, acc[fm][fn][1] + b1);
            float2 o1 = make_float2(acc[fm][fn][2] + b0, acc[fm][fn][3] + b1);
            *reinterpret_cast<float2*>(&Cm[(size_t)row * 256 + col]) = o0;
            *reinterpret_cast<float2*>(&Cm[(size_t)(row + 8) * 256 + col]) = o1;
        }
    }
}

// ------------------------- fused edge pass: alpha + exp + unnormalized scatter -------------------------
// Softmax division deferred: out = (sum_e ex*(v+e)) / (sum_e ex), per (dst, head).
// Warp per edge; lane l covers channels [8l, 8l+8); heads are lane groups of 8.
__global__ void edge_fused_kernel(const int* __restrict__ src, const int* __restrict__ dst,
                                  const float* __restrict__ ea, const float* __restrict__ We) {
    __shared__ float sWe[256];
    int tid = threadIdx.x;
    sWe[tid] = We[tid];
    __syncthreads();
    int warp = tid >> 5, lane = tid & 31;
    int e = blockIdx.x * 8 + warp;
    if (e >= EE) return;
    int s = src[e], d = dst[e];
    float av = ea[e];
    int head = lane >> 3, sub = lane & 7;
    int ch = head * 64 + sub * 8;
    const float4* qp = reinterpret_cast<const float4*>(&g_q[d * 256 + ch]);
    const float4* kp = reinterpret_cast<const float4*>(&g_k[s * 256 + ch]);
    const float4* vp = reinterpret_cast<const float4*>(&g_v[s * 256 + ch]);
    const float4* wp = reinterpret_cast<const float4*>(&sWe[ch]);

    float4 q4[2], k4[2], v4[2], w4[2];
#pragma unroll
    for (int t = 0; t < 2; t++) { q4[t] = qp[t]; k4[t] = kp[t]; v4[t] = vp[t]; w4[t] = wp[t]; }

    float p = 0.f;
#pragma unroll
    for (int t = 0; t < 2; t++) {
        p += q4[t].x * (k4[t].x + av * w4[t].x) + q4[t].y * (k4[t].y + av * w4[t].y) +
             q4[t].z * (k4[t].z + av * w4[t].z) + q4[t].w * (k4[t].w + av * w4[t].w);
    }
    // full reduce within each 8-lane head group (xor keeps it inside the group)
    p += __shfl_xor_sync(0xffffffffu, p, 4);
    p += __shfl_xor_sync(0xffffffffu, p, 2);
    p += __shfl_xor_sync(0xffffffffu, p, 1);
    float ex = expf(p * 0.125f);  // scale = 1/sqrt(64); max-shift cancels in softmax ratio

#pragma unroll
    for (int t = 0; t < 2; t++) {
        float4 m;
        m.x = (v4[t].x + av * w4[t].x) * ex;
        m.y = (v4[t].y + av * w4[t].y) * ex;
        m.z = (v4[t].z + av * w4[t].z) * ex;
        m.w = (v4[t].w + av * w4[t].w) * ex;
        atomicAdd(reinterpret_cast<float4*>(&g_msg[d * 256 + ch + t * 4]), m);
    }
    if (sub == 0) atomicAdd(&g_den[d * 4 + head], ex);
}

// ------------------------- beta-gated skip combine (with deferred softmax division) -------------------------
__global__ void combine_kernel(const float* __restrict__ Wb) {
    __shared__ float sWb[768];
    int tid = threadIdx.x;
    sWb[tid] = Wb[tid];
    sWb[tid + 256] = Wb[tid + 256];
    sWb[tid + 512] = Wb[tid + 512];
    __syncthreads();
    int warp = tid >> 5, lane = tid & 31;
    int n = blockIdx.x * 8 + warp;
    if (n >= NN) return;
    int ch = lane * 8;
    int head = lane >> 3;
    float den = g_den[n * 4 + head];
    float inv = (den > 0.f) ? (1.f / den) : 0.f;  // isolated node -> out = 0 (matches reference)
    float4 o0 = *reinterpret_cast<const float4*>(&g_msg[n * 256 + ch]);
    float4 o1 = *reinterpret_cast<const float4*>(&g_msg[n * 256 + ch + 4]);
    float4 x0 = *reinterpret_cast<const float4*>(&g_xr[n * 256 + ch]);
    float4 x1 = *reinterpret_cast<const float4*>(&g_xr[n * 256 + ch + 4]);
    float ov[8] = {o0.x * inv, o0.y * inv, o0.z * inv, o0.w * inv,
                   o1.x * inv, o1.y * inv, o1.z * inv, o1.w * inv};
    float xv[8] = {x0.x, x0.y, x0.z, x0.w, x1.x, x1.y, x1.z, x1.w};
    float p = 0.f;
#pragma unroll
    for (int i = 0; i < 8; i++)
        p += ov[i] * sWb[ch + i] + xv[i] * sWb[256 + ch + i] + (ov[i] - xv[i]) * sWb[512 + ch + i];
#pragma unroll
    for (int off = 16; off; off >>= 1) p += __shfl_xor_sync(0xffffffffu, p, off);
    float beta = 1.f / (1.f + expf(-p));
    float r[8];
#pragma unroll
    for (int i = 0; i < 8; i++) r[i] = beta * xv[i] + (1.f - beta) * ov[i];
    *reinterpret_cast<float4*>(&g_h[n * 256 + ch]) = make_float4(r[0], r[1], r[2], r[3]);
    *reinterpret_cast<float4*>(&g_h[n * 256 + ch + 4]) = make_float4(r[4], r[5], r[6], r[7]);
}

// ------------------------- batchnorm column stats -------------------------
__global__ void bn_reduce_kernel() {
    int d = threadIdx.x;
    int r0 = blockIdx.x * 128;
    float s = 0.f, s2 = 0.f;
    for (int r = 0; r < 128; r++) {
        float v = g_h[(r0 + r) * 256 + d];
        s += v;
        s2 += v * v;
    }
    atomicAdd(&g_colstats[d], s);
    atomicAdd(&g_colstats[256 + d], s2);
}

// ------------------------- BN apply + ELU -------------------------
__global__ void bn_apply_kernel(const float* __restrict__ gamma, const float* __restrict__ beta) {
    int i = blockIdx.x * blockDim.x + threadIdx.x;
    if (i >= NN * DD) return;
    int d = i & 255;
    float mu = g_colstats[d] * (1.f / NN);
    float var = g_colstats[256 + d] * (1.f / NN) - mu * mu;
    float y = gamma[d] * (g_h[i] - mu) * rsqrtf(var + BN_EPS) + beta[d];
    g_h[i] = y > 0.f ? y : expm1f(y);
}

// ------------------------- readout: gate softmax denom -------------------------
__global__ void gate_kernel(const int* __restrict__ batch, const float* __restrict__ gW,
                            const float* __restrict__ gb) {
    int tid = threadIdx.x;
    int warp = tid >> 5, lane = tid & 31;
    int n = blockIdx.x * 8 + warp;
    if (n >= NN) return;
    float p = 0.f;
#pragma unroll
    for (int t = 0; t < 8; t++) {
        int ch = lane + t * 32;
        p += g_h[n * 256 + ch] * gW[ch];
    }
#pragma unroll
    for (int off = 16; off; off >>= 1) p += __shfl_xor_sync(0xffffffffu, p, off);
    if (lane == 0) {
        float ex = expf(p + gb[0]);
        g_gate[n] = ex;
        atomicAdd(&g_gden[batch[n]], ex);
    }
}

// ------------------------- readout: weighted pooling -------------------------
__global__ void pool_kernel(const int* __restrict__ batch) {
    int i = blockIdx.x * blockDim.x + threadIdx.x;
    if (i >= NN * 64) return;
    int n = i >> 6, c4 = (i & 63) * 4;
    int g = batch[n];
    float w = g_gate[n] / g_gden[g];
    float4 hv = *reinterpret_cast<const float4*>(&g_h[n * 256 + c4]);
    float4 m = make_float4(hv.x * w, hv.y * w, hv.z * w, hv.w * w);
    atomicAdd(reinterpret_cast<float4*>(&g_hG[g * 256 + c4]), m);
}

// ------------------------- decoder -------------------------
__global__ void final_kernel(const float* __restrict__ dW, const float* __restrict__ db,
                             const float* __restrict__ ob, float* __restrict__ out) {
    __shared__ float red[256];
    int g = blockIdx.x, t = threadIdx.x;
    red[t] = g_hG[g * 256 + t] * dW[t];
    __syncthreads();
    for (int s = 128; s > 0; s >>= 1) {
        if (t < s) red[t] += red[t + s];
        __syncthreads();
    }
    if (t == 0) out[g] = red[0] + db[0] + ob[0];
}

// ------------------------- launcher -------------------------
extern "C" void kernel_launch(void* const* d_in, const int* in_sizes, int n_in,
                              void* d_out, int out_size) {
    const float* x     = (const float*)d_in[0];
    const int*   ei    = (const int*)d_in[1];
    const float* ea    = (const float*)d_in[2];
    const int*   batch = (const int*)d_in[3];
    const float* encW  = (const float*)d_in[4];
    const float* encb  = (const float*)d_in[5];
    const float* Wq    = (const float*)d_in[6];
    const float* bq    = (const float*)d_in[7];
    const float* Wk    = (const float*)d_in[8];
    const float* bk    = (const float*)d_in[9];
    const float* Wv    = (const float*)d_in[10];
    const float* bv    = (const float*)d_in[11];
    const float* We    = (const float*)d_in[12];
    const float* Wskip = (const float*)d_in[13];
    const float* bskip = (const float*)d_in[14];
    const float* Wbeta = (const float*)d_in[15];
    const float* bng   = (const float*)d_in[16];
    const float* bnb   = (const float*)d_in[17];
    const float* gW    = (const float*)d_in[18];
    const float* gb    = (const float*)d_in[19];
    const float* dW    = (const float*)d_in[20];
    const float* db    = (const float*)d_in[21];
    const float* ob    = (const float*)d_in[22];
    float* out = (float*)d_out;

    const int* src = ei;        // edge_index[0]
    const int* dst = ei + EE;   // edge_index[1]

    const int TPB = 256;
    const int ND_BLOCKS = (NN * DD) / TPB;          // 32768
    dim3 gemm_grid(2, 256);

    encoder_kernel<<<ND_BLOCKS, TPB>>>(x, encW, encb);

    for (int l = 0; l < 2; l++) {
        const float* Wq_l = Wq + (size_t)l * DD * DD;
        const float* Wk_l = Wk + (size_t)l * DD * DD;
        const float* Wv_l = Wv + (size_t)l * DD * DD;
        const float* Ws_l = Wskip + (size_t)l * DD * DD;
        mma_gemm_bias<<<gemm_grid, TPB>>>(Wq_l, bq + l * DD, 0);
        mma_gemm_bias<<<gemm_grid, TPB>>>(Wk_l, bk + l * DD, 1);
        mma_gemm_bias<<<gemm_grid, TPB>>>(Wv_l, bv + l * DD, 2);
        mma_gemm_bias<<<gemm_grid, TPB>>>(Ws_l, bskip + l * DD, 3);

        zero_layer_kernel<<<ND_BLOCKS, TPB>>>();

        edge_fused_kernel<<<EE / 8, TPB>>>(src, dst, ea, We + l * DD);

        combine_kernel<<<NN / 8, TPB>>>(Wbeta + l * 3 * DD);
        bn_reduce_kernel<<<256, TPB>>>();
        bn_apply_kernel<<<ND_BLOCKS, TPB>>>(bng + l * DD, bnb + l * DD);
    }

    zero_readout_kernel<<<32, TPB>>>();
    gate_kernel<<<NN / 8, TPB>>>(batch, gW, gb);
    pool_kernel<<<(NN * 64) / TPB, TPB>>>(batch);
    final_kernel<<<GG, TPB>>>(dW, db, ob, out);
}

// round 8
// speedup vs baseline: 1.4817x; 1.4817x over previous
#include <cuda_runtime.h>
#include <math.h>
#include <stdint.h>

#define NN 32768
#define EE 262144
#define DD 256
#define HH 4
#define GG 32
#define BN_EPS 1e-5f

// ------------------------- scratch (device globals) -------------------------
__device__ float g_h[NN * DD];
__device__ uint32_t g_ht[NN * DD];     // tf32-rounded copy of g_h (GEMM A operand)
__device__ uint32_t g_wt[8 * DD * DD]; // tf32 weights: (layer*4 + {q,k,v,skip})
__device__ float g_q[NN * DD];
__device__ float g_k[NN * DD];
__device__ float g_v[NN * DD];
__device__ float g_xr[NN * DD];
__device__ float g_msg[NN * DD];       // UNNORMALIZED attention aggregate: sum ex*(v+e)
__device__ float g_den[NN * HH];       // softmax denominators per dst node/head
__device__ float g_colstats[2 * DD];   // [0..255] colsum, [256..511] colsumsq
__device__ float g_gate[NN];           // exp(gate) per node
__device__ float g_gden[GG];           // per-graph softmax denom
__device__ float g_hG[GG * DD];        // pooled per-graph embedding

__device__ __forceinline__ uint32_t f2tf32(float f) {
    uint32_t r;
    asm("cvt.rna.tf32.f32 %0, %1;" : "=r"(r) : "f"(f));
    return r;
}

// ------------------------- zero kernels -------------------------
__global__ void zero_layer_kernel() {
    int i = blockIdx.x * blockDim.x + threadIdx.x;
    if (i < NN * DD) g_msg[i] = 0.f;
    if (i < NN * HH) g_den[i] = 0.f;
    if (i < 2 * DD) g_colstats[i] = 0.f;
}

__global__ void zero_readout_kernel() {
    int i = blockIdx.x * blockDim.x + threadIdx.x;
    if (i < GG * DD) g_hG[i] = 0.f;
    if (i < GG) g_gden[i] = 0.f;
}

// ------------------------- weight prep: tf32-round all 8 GEMM weights once -------------------------
__global__ void prep_w_kernel(const float* __restrict__ Wq, const float* __restrict__ Wk,
                              const float* __restrict__ Wv, const float* __restrict__ Ws) {
    int m = blockIdx.y;            // 0..7 : layer*4 + which
    int i = blockIdx.x * blockDim.x + threadIdx.x;
    int l = m >> 2, w = m & 3;
    const float* S = (w == 0) ? Wq : (w == 1) ? Wk : (w == 2) ? Wv : Ws;
    g_wt[m * DD * DD + i] = f2tf32(S[l * DD * DD + i]);
}

// ------------------------- encoder: h = x @ enc_W + enc_b (+ tf32 copy) -------------------------
__global__ void encoder_kernel(const float* __restrict__ x,
                               const float* __restrict__ W,
                               const float* __restrict__ b) {
    int i = blockIdx.x * blockDim.x + threadIdx.x;
    if (i >= NN * DD) return;
    int n = i >> 8, d = i & 255;
    float h = x[n * 2] * W[d] + x[n * 2 + 1] * W[DD + d] + b[d];
    g_h[i] = h;
    g_ht[i] = f2tf32(h);
}

// ------------------------- TF32 tensor-core GEMM, zero in-loop conversions -------------------------
// C = tf32(g_h)[32768x256] @ tf32(W)[256x256] + bias via mma.sync m16n8k8.
// BM=128, BN=128, BK=16; 8 warps (2 m x 4 n), warp tile 64x32.
#define SA 20    // A smem stride (words): conflict-free, 16B-aligned slots
#define SB 136   // B smem stride (words): conflict-free

__device__ __forceinline__ void cp16(uint32_t s, const void* g) {
    asm volatile("cp.async.ca.shared.global [%0], [%1], 16;" :: "r"(s), "l"(g));
}

__device__ __forceinline__ void mma8(float* c, const uint32_t* a, const uint32_t* b) {
    asm volatile(
        "mma.sync.aligned.m16n8k8.row.col.f32.tf32.tf32.f32 "
        "{%0,%1,%2,%3}, {%4,%5,%6,%7}, {%8,%9}, {%0,%1,%2,%3};"
        : "+f"(c[0]), "+f"(c[1]), "+f"(c[2]), "+f"(c[3])
        : "r"(a[0]), "r"(a[1]), "r"(a[2]), "r"(a[3]), "r"(b[0]), "r"(b[1]));
}

__global__ __launch_bounds__(256, 2) void mma_gemm_bias(const float* __restrict__ bias,
                                                        int matid) {
    __shared__ uint32_t As[2][128 * SA];
    __shared__ uint32_t Bs[2][16 * SB];

    int outsel = matid & 3;
    float* Cm = (outsel == 0) ? g_q : (outsel == 1) ? g_k : (outsel == 2) ? g_v : g_xr;
    const uint32_t* A = g_ht;
    const uint32_t* B = g_wt + (size_t)matid * DD * DD;

    int tid = threadIdx.x;
    int warp = tid >> 5, lane = tid & 31;
    int gid = lane >> 2, tig = lane & 3;
    int warp_m = (warp & 1) * 64;
    int warp_n = (warp >> 1) * 32;
    int bm = blockIdx.y * 128, bn = blockIdx.x * 128;

    float acc[4][4][4];
#pragma unroll
    for (int i = 0; i < 4; i++)
#pragma unroll
        for (int j = 0; j < 4; j++)
#pragma unroll
            for (int r = 0; r < 4; r++) acc[i][j][r] = 0.f;

    uint32_t as_base = (uint32_t)__cvta_generic_to_shared(&As[0][0]);
    uint32_t bs_base = (uint32_t)__cvta_generic_to_shared(&Bs[0][0]);

    int a_row = tid >> 2, a_kq = (tid & 3) * 4;
    int b_row = tid >> 5, b_nq = (tid & 31) * 4;

    auto load_tiles = [&](int buf, int k0) {
        cp16(as_base + (uint32_t)(buf * 128 * SA + a_row * SA + a_kq) * 4u,
             &A[(size_t)(bm + a_row) * 256 + k0 + a_kq]);
        cp16(as_base + (uint32_t)(buf * 128 * SA + (a_row + 64) * SA + a_kq) * 4u,
             &A[(size_t)(bm + a_row + 64) * 256 + k0 + a_kq]);
        cp16(bs_base + (uint32_t)(buf * 16 * SB + b_row * SB + b_nq) * 4u,
             &B[(size_t)(k0 + b_row) * 256 + bn + b_nq]);
        cp16(bs_base + (uint32_t)(buf * 16 * SB + (b_row + 8) * SB + b_nq) * 4u,
             &B[(size_t)(k0 + b_row + 8) * 256 + bn + b_nq]);
    };

    load_tiles(0, 0);
    asm volatile("cp.async.commit_group;");

    for (int it = 0; it < 16; it++) {
        int buf = it & 1;
        if (it + 1 < 16) load_tiles(buf ^ 1, (it + 1) * 16);
        asm volatile("cp.async.commit_group;");
        asm volatile("cp.async.wait_group 1;");
        __syncthreads();

        const uint32_t* Ab = &As[buf][0];
        const uint32_t* Bb = &Bs[buf][0];
#pragma unroll
        for (int ks = 0; ks < 16; ks += 8) {
            uint32_t bfr[4][2];
#pragma unroll
            for (int fn = 0; fn < 4; fn++) {
                int n = warp_n + fn * 8 + gid;
                bfr[fn][0] = Bb[(ks + tig) * SB + n];
                bfr[fn][1] = Bb[(ks + tig + 4) * SB + n];
            }
            uint32_t afr[4][4];
#pragma unroll
            for (int fm = 0; fm < 4; fm++) {
                int m = warp_m + fm * 16 + gid;
                afr[fm][0] = Ab[m * SA + ks + tig];
                afr[fm][1] = Ab[(m + 8) * SA + ks + tig];
                afr[fm][2] = Ab[m * SA + ks + tig + 4];
                afr[fm][3] = Ab[(m + 8) * SA + ks + tig + 4];
            }
#pragma unroll
            for (int fm = 0; fm < 4; fm++)
#pragma unroll
                for (int fn = 0; fn < 4; fn++) mma8(acc[fm][fn], afr[fm], bfr[fn]);
        }
        __syncthreads();
    }

#pragma unroll
    for (int fm = 0; fm < 4; fm++) {
        int row = bm + warp_m + fm * 16 + gid;
#pragma unroll
        for (int fn = 0; fn < 4; fn++) {
            int col = bn + warp_n + fn * 8 + tig * 2;
            float b0 = bias[col], b1 = bias[col + 1];
            float2 o0 = make_float2(acc[fm][fn][0] + b0, acc[fm][fn][1] + b1);
            float2 o1 = make_float2(acc[fm][fn][2] + b0, acc[fm][fn][3] + b1);
            *reinterpret_cast<float2*>(&Cm[(size_t)row * 256 + col]) = o0;
            *reinterpret_cast<float2*>(&Cm[(size_t)(row + 8) * 256 + col]) = o1;
        }
    }
}

// ------------------------- fused edge pass -------------------------
// out = (sum_e ex*(v+e)) / (sum_e ex) per (dst, head); division deferred to combine.
__global__ void edge_fused_kernel(const int* __restrict__ src, const int* __restrict__ dst,
                                  const float* __restrict__ ea, const float* __restrict__ We) {
    __shared__ float sWe[256];
    int tid = threadIdx.x;
    sWe[tid] = We[tid];
    __syncthreads();
    int warp = tid >> 5, lane = tid & 31;
    int e = blockIdx.x * 8 + warp;
    if (e >= EE) return;
    int s = src[e], d = dst[e];
    float av = ea[e];
    int head = lane >> 3, sub = lane & 7;
    int ch = head * 64 + sub * 8;
    const float4* qp = reinterpret_cast<const float4*>(&g_q[d * 256 + ch]);
    const float4* kp = reinterpret_cast<const float4*>(&g_k[s * 256 + ch]);
    const float4* vp = reinterpret_cast<const float4*>(&g_v[s * 256 + ch]);
    const float4* wp = reinterpret_cast<const float4*>(&sWe[ch]);

    float4 q4[2], k4[2], v4[2], w4[2];
#pragma unroll
    for (int t = 0; t < 2; t++) { q4[t] = qp[t]; k4[t] = kp[t]; v4[t] = vp[t]; w4[t] = wp[t]; }

    float p = 0.f;
#pragma unroll
    for (int t = 0; t < 2; t++) {
        p += q4[t].x * (k4[t].x + av * w4[t].x) + q4[t].y * (k4[t].y + av * w4[t].y) +
             p * 0.f + q4[t].z * (k4[t].z + av * w4[t].z) + q4[t].w * (k4[t].w + av * w4[t].w);
    }
    p += __shfl_xor_sync(0xffffffffu, p, 4);
    p += __shfl_xor_sync(0xffffffffu, p, 2);
    p += __shfl_xor_sync(0xffffffffu, p, 1);
    float ex = expf(p * 0.125f);  // scale = 1/sqrt(64); max-shift cancels in softmax ratio

#pragma unroll
    for (int t = 0; t < 2; t++) {
        float4 m;
        m.x = (v4[t].x + av * w4[t].x) * ex;
        m.y = (v4[t].y + av * w4[t].y) * ex;
        m.z = (v4[t].z + av * w4[t].z) * ex;
        m.w = (v4[t].w + av * w4[t].w) * ex;
        atomicAdd(reinterpret_cast<float4*>(&g_msg[d * 256 + ch + t * 4]), m);
    }
    if (sub == 0) atomicAdd(&g_den[d * 4 + head], ex);
}

// ------------------------- combine (deferred softmax div + beta skip) + BN stats -------------------------
// 256 blocks x 256 threads; each warp processes 16 nodes; per-thread register stats
// for its fixed 8 channels, cross-warp smem reduce, one global atomic pair per channel.
__global__ __launch_bounds__(256) void combine_stats_kernel(const float* __restrict__ Wb) {
    __shared__ float sWb[768];
    __shared__ float sS[8 * 256];
    __shared__ float sS2[8 * 256];
    int tid = threadIdx.x;
    sWb[tid] = Wb[tid];
    sWb[tid + 256] = Wb[tid + 256];
    sWb[tid + 512] = Wb[tid + 512];
    __syncthreads();
    int warp = tid >> 5, lane = tid & 31;
    int ch = lane * 8;
    int head = lane >> 3;
    float s[8], s2[8];
#pragma unroll
    for (int i = 0; i < 8; i++) { s[i] = 0.f; s2[i] = 0.f; }

    for (int it = 0; it < 16; it++) {
        int n = blockIdx.x * 128 + it * 8 + warp;
        float den = g_den[n * 4 + head];
        float inv = (den > 0.f) ? (1.f / den) : 0.f;  // isolated node -> out = 0
        float4 o0 = *reinterpret_cast<const float4*>(&g_msg[n * 256 + ch]);
        float4 o1 = *reinterpret_cast<const float4*>(&g_msg[n * 256 + ch + 4]);
        float4 x0 = *reinterpret_cast<const float4*>(&g_xr[n * 256 + ch]);
        float4 x1 = *reinterpret_cast<const float4*>(&g_xr[n * 256 + ch + 4]);
        float ov[8] = {o0.x * inv, o0.y * inv, o0.z * inv, o0.w * inv,
                       o1.x * inv, o1.y * inv, o1.z * inv, o1.w * inv};
        float xv[8] = {x0.x, x0.y, x0.z, x0.w, x1.x, x1.y, x1.z, x1.w};
        float p = 0.f;
#pragma unroll
        for (int i = 0; i < 8; i++)
            p += ov[i] * sWb[ch + i] + xv[i] * sWb[256 + ch + i] + (ov[i] - xv[i]) * sWb[512 + ch + i];
#pragma unroll
        for (int off = 16; off; off >>= 1) p += __shfl_xor_sync(0xffffffffu, p, off);
        float beta = 1.f / (1.f + expf(-p));
        float r[8];
#pragma unroll
        for (int i = 0; i < 8; i++) {
            r[i] = beta * xv[i] + (1.f - beta) * ov[i];
            s[i] += r[i];
            s2[i] += r[i] * r[i];
        }
        *reinterpret_cast<float4*>(&g_h[n * 256 + ch]) = make_float4(r[0], r[1], r[2], r[3]);
        *reinterpret_cast<float4*>(&g_h[n * 256 + ch + 4]) = make_float4(r[4], r[5], r[6], r[7]);
    }
#pragma unroll
    for (int i = 0; i < 8; i++) {
        sS[warp * 256 + ch + i] = s[i];
        sS2[warp * 256 + ch + i] = s2[i];
    }
    __syncthreads();
    float ts = 0.f, ts2 = 0.f;
#pragma unroll
    for (int w = 0; w < 8; w++) {
        ts += sS[w * 256 + tid];
        ts2 += sS2[w * 256 + tid];
    }
    atomicAdd(&g_colstats[tid], ts);
    atomicAdd(&g_colstats[256 + tid], ts2);
}

// ------------------------- BN apply + ELU (layer 1: also writes tf32 copy) -------------------------
__global__ void bn_apply_l1_kernel(const float* __restrict__ gamma, const float* __restrict__ beta) {
    int i = blockIdx.x * blockDim.x + threadIdx.x;
    if (i >= NN * DD) return;
    int d = i & 255;
    float mu = g_colstats[d] * (1.f / NN);
    float var = g_colstats[256 + d] * (1.f / NN) - mu * mu;
    float y = gamma[d] * (g_h[i] - mu) * rsqrtf(var + BN_EPS) + beta[d];
    float r = y > 0.f ? y : expm1f(y);
    g_h[i] = r;
    g_ht[i] = f2tf32(r);
}

// ------------------------- BN apply + ELU + fused gate (layer 2) -------------------------
// warp per node: BN+ELU per lane's 8 channels, gate dot-product reduce, exp + gden atomic.
__global__ void bn_apply_gate_kernel(const float* __restrict__ gamma, const float* __restrict__ beta,
                                     const int* __restrict__ batch, const float* __restrict__ gW,
                                     const float* __restrict__ gb) {
    __shared__ float sgW[256];
    int tid = threadIdx.x;
    sgW[tid] = gW[tid];
    __syncthreads();
    int warp = tid >> 5, lane = tid & 31;
    int n = blockIdx.x * 8 + warp;
    if (n >= NN) return;
    int ch = lane * 8;
    float p = 0.f;
    float r[8];
#pragma unroll
    for (int i = 0; i < 8; i++) {
        int d = ch + i;
        float mu = g_colstats[d] * (1.f / NN);
        float var = g_colstats[256 + d] * (1.f / NN) - mu * mu;
        float y = gamma[d] * (g_h[n * 256 + d] - mu) * rsqrtf(var + BN_EPS) + beta[d];
        r[i] = y > 0.f ? y : expm1f(y);
        p += r[i] * sgW[d];
    }
    *reinterpret_cast<float4*>(&g_h[n * 256 + ch]) = make_float4(r[0], r[1], r[2], r[3]);
    *reinterpret_cast<float4*>(&g_h[n * 256 + ch + 4]) = make_float4(r[4], r[5], r[6], r[7]);
#pragma unroll
    for (int off = 16; off; off >>= 1) p += __shfl_xor_sync(0xffffffffu, p, off);
    if (lane == 0) {
        float ex = expf(p + gb[0]);
        g_gate[n] = ex;
        atomicAdd(&g_gden[batch[n]], ex);
    }
}

// ------------------------- readout: weighted pooling -------------------------
__global__ void pool_kernel(const int* __restrict__ batch) {
    int i = blockIdx.x * blockDim.x + threadIdx.x;
    if (i >= NN * 64) return;
    int n = i >> 6, c4 = (i & 63) * 4;
    int g = batch[n];
    float w = g_gate[n] / g_gden[g];
    float4 hv = *reinterpret_cast<const float4*>(&g_h[n * 256 + c4]);
    float4 m = make_float4(hv.x * w, hv.y * w, hv.z * w, hv.w * w);
    atomicAdd(reinterpret_cast<float4*>(&g_hG[g * 256 + c4]), m);
}

// ------------------------- decoder -------------------------
__global__ void final_kernel(const float* __restrict__ dW, const float* __restrict__ db,
                             const float* __restrict__ ob, float* __restrict__ out) {
    __shared__ float red[256];
    int g = blockIdx.x, t = threadIdx.x;
    red[t] = g_hG[g * 256 + t] * dW[t];
    __syncthreads();
    for (int s = 128; s > 0; s >>= 1) {
        if (t < s) red[t] += red[t + s];
        __syncthreads();
    }
    if (t == 0) out[g] = red[0] + db[0] + ob[0];
}

// ------------------------- launcher -------------------------
extern "C" void kernel_launch(void* const* d_in, const int* in_sizes, int n_in,
                              void* d_out, int out_size) {
    const float* x     = (const float*)d_in[0];
    const int*   ei    = (const int*)d_in[1];
    const float* ea    = (const float*)d_in[2];
    const int*   batch = (const int*)d_in[3];
    const float* encW  = (const float*)d_in[4];
    const float* encb  = (const float*)d_in[5];
    const float* Wq    = (const float*)d_in[6];
    const float* bq    = (const float*)d_in[7];
    const float* Wk    = (const float*)d_in[8];
    const float* bk    = (const float*)d_in[9];
    const float* Wv    = (const float*)d_in[10];
    const float* bv    = (const float*)d_in[11];
    const float* We    = (const float*)d_in[12];
    const float* Wskip = (const float*)d_in[13];
    const float* bskip = (const float*)d_in[14];
    const float* Wbeta = (const float*)d_in[15];
    const float* bng   = (const float*)d_in[16];
    const float* bnb   = (const float*)d_in[17];
    const float* gW    = (const float*)d_in[18];
    const float* gb    = (const float*)d_in[19];
    const float* dW    = (const float*)d_in[20];
    const float* db    = (const float*)d_in[21];
    const float* ob    = (const float*)d_in[22];
    float* out = (float*)d_out;

    const int* src = ei;        // edge_index[0]
    const int* dst = ei + EE;   // edge_index[1]

    const int TPB = 256;
    const int ND_BLOCKS = (NN * DD) / TPB;
    dim3 gemm_grid(2, 256);

    prep_w_kernel<<<dim3(DD * DD / TPB, 8), TPB>>>(Wq, Wk, Wv, Wskip);
    zero_readout_kernel<<<32, TPB>>>();
    encoder_kernel<<<ND_BLOCKS, TPB>>>(x, encW, encb);

    for (int l = 0; l < 2; l++) {
        mma_gemm_bias<<<gemm_grid, TPB>>>(bq + l * DD, l * 4 + 0);
        mma_gemm_bias<<<gemm_grid, TPB>>>(bk + l * DD, l * 4 + 1);
        mma_gemm_bias<<<gemm_grid, TPB>>>(bv + l * DD, l * 4 + 2);
        mma_gemm_bias<<<gemm_grid, TPB>>>(bskip + l * DD, l * 4 + 3);

        zero_layer_kernel<<<ND_BLOCKS, TPB>>>();

        edge_fused_kernel<<<EE / 8, TPB>>>(src, dst, ea, We + l * DD);

        combine_stats_kernel<<<256, TPB>>>(Wbeta + l * 3 * DD);

        if (l == 0) {
            bn_apply_l1_kernel<<<ND_BLOCKS, TPB>>>(bng, bnb);
        } else {
            bn_apply_gate_kernel<<<NN / 8, TPB>>>(bng + DD, bnb + DD, batch, gW, gb);
        }
    }

    pool_kernel<<<(NN * 64) / TPB, TPB>>>(batch);
    final_kernel<<<GG, TPB>>>(dW, db, ob, out);
}

// round 9
// speedup vs baseline: 1.6106x; 1.0870x over previous
#include <cuda_runtime.h>
#include <math.h>
#include <stdint.h>

#define NN 32768
#define EE 262144
#define DD 256
#define HH 4
#define GG 32
#define BN_EPS 1e-5f

// ------------------------- scratch (device globals) -------------------------
__device__ float g_h[NN * DD];
__device__ uint32_t g_ht[NN * DD];     // tf32-rounded copy of g_h (GEMM A operand)
__device__ uint32_t g_wt[8 * DD * DD]; // tf32 weights: (layer*4 + {q,k,v,skip})
__device__ float g_q[NN * DD];
__device__ float g_k[NN * DD];
__device__ float g_v[NN * DD];
__device__ float g_xr[NN * DD];
__device__ float g_colstats[2 * DD];   // [0..255] colsum, [256..511] colsumsq
__device__ float g_gate[NN];           // exp(gate) per node
__device__ float g_gden[GG];           // per-graph softmax denom
__device__ float g_hG[GG * DD];        // pooled per-graph embedding
// CSR by dst (built once, reused for both layers)
__device__ int g_rowptr[NN + 1];
__device__ int g_cnt[NN];
__device__ int g_esrc[EE];             // src node per edge, dst-sorted
__device__ float g_eav[EE];            // edge_attr per edge, dst-sorted

__device__ __forceinline__ uint32_t f2tf32(float f) {
    uint32_t r;
    asm("cvt.rna.tf32.f32 %0, %1;" : "=r"(r) : "f"(f));
    return r;
}

// ------------------------- small zero kernels -------------------------
__global__ void zero_cnt_kernel() {
    int i = blockIdx.x * blockDim.x + threadIdx.x;
    if (i < NN) g_cnt[i] = 0;
}
__global__ void zero_stats_kernel() {
    int i = blockIdx.x * blockDim.x + threadIdx.x;
    if (i < 2 * DD) g_colstats[i] = 0.f;
}
__global__ void zero_readout_kernel() {
    int i = blockIdx.x * blockDim.x + threadIdx.x;
    if (i < GG * DD) g_hG[i] = 0.f;
    if (i < GG) g_gden[i] = 0.f;
}

// ------------------------- CSR build -------------------------
__global__ void deg_hist_kernel(const int* __restrict__ dst) {
    int e = blockIdx.x * blockDim.x + threadIdx.x;
    if (e < EE) atomicAdd(&g_cnt[dst[e]], 1);
}

// single-block exclusive scan of g_cnt -> g_rowptr (NN entries, 1024 threads, 32 chunks)
__global__ void scan_kernel() {
    __shared__ int swarp[32];
    __shared__ int carry;
    int tid = threadIdx.x;
    int lane = tid & 31, w = tid >> 5;
    if (tid == 0) carry = 0;
    __syncthreads();
    for (int base = 0; base < NN; base += 1024) {
        int x = g_cnt[base + tid];
#pragma unroll
        for (int o = 1; o < 32; o <<= 1) {
            int y = __shfl_up_sync(0xffffffffu, x, o);
            if (lane >= o) x += y;
        }
        if (lane == 31) swarp[w] = x;
        __syncthreads();
        if (w == 0) {
            int y = swarp[lane];
#pragma unroll
            for (int o = 1; o < 32; o <<= 1) {
                int z = __shfl_up_sync(0xffffffffu, y, o);
                if (lane >= o) y += z;
            }
            swarp[lane] = y;
        }
        __syncthreads();
        int incl = x + (w > 0 ? swarp[w - 1] : 0) + carry;
        g_rowptr[base + tid + 1] = incl;
        __syncthreads();
        if (tid == 1023) carry = incl;
        __syncthreads();
    }
    if (tid == 0) g_rowptr[0] = 0;
}

__global__ void scatter_kernel(const int* __restrict__ src, const int* __restrict__ dst,
                               const float* __restrict__ ea) {
    int e = blockIdx.x * blockDim.x + threadIdx.x;
    if (e >= EE) return;
    int d = dst[e];
    int pos = g_rowptr[d] + atomicAdd(&g_cnt[d], 1);
    g_esrc[pos] = src[e];
    g_eav[pos] = ea[e];
}

// ------------------------- weight prep: tf32-round all 8 GEMM weights once -------------------------
__global__ void prep_w_kernel(const float* __restrict__ Wq, const float* __restrict__ Wk,
                              const float* __restrict__ Wv, const float* __restrict__ Ws) {
    int m = blockIdx.y;            // 0..7 : layer*4 + which
    int i = blockIdx.x * blockDim.x + threadIdx.x;
    int l = m >> 2, w = m & 3;
    const float* S = (w == 0) ? Wq : (w == 1) ? Wk : (w == 2) ? Wv : Ws;
    g_wt[m * DD * DD + i] = f2tf32(S[l * DD * DD + i]);
}

// ------------------------- encoder: h = x @ enc_W + enc_b (+ tf32 copy) -------------------------
__global__ void encoder_kernel(const float* __restrict__ x,
                               const float* __restrict__ W,
                               const float* __restrict__ b) {
    int i = blockIdx.x * blockDim.x + threadIdx.x;
    if (i >= NN * DD) return;
    int n = i >> 8, d = i & 255;
    float h = x[n * 2] * W[d] + x[n * 2 + 1] * W[DD + d] + b[d];
    g_h[i] = h;
    g_ht[i] = f2tf32(h);
}

// ------------------------- TF32 tensor-core GEMM: all 4 matrices in one launch -------------------------
// C[mat] = tf32(g_h) @ tf32(W[mat]) + bias[mat]; grid (8, 256): x = mat*2 + n-half.
#define SA 20
#define SB 136

__device__ __forceinline__ void cp16(uint32_t s, const void* g) {
    asm volatile("cp.async.ca.shared.global [%0], [%1], 16;" :: "r"(s), "l"(g));
}

__device__ __forceinline__ void mma8(float* c, const uint32_t* a, const uint32_t* b) {
    asm volatile(
        "mma.sync.aligned.m16n8k8.row.col.f32.tf32.tf32.f32 "
        "{%0,%1,%2,%3}, {%4,%5,%6,%7}, {%8,%9}, {%0,%1,%2,%3};"
        : "+f"(c[0]), "+f"(c[1]), "+f"(c[2]), "+f"(c[3])
        : "r"(a[0]), "r"(a[1]), "r"(a[2]), "r"(a[3]), "r"(b[0]), "r"(b[1]));
}

__global__ __launch_bounds__(256, 2) void mma_gemm4(const float* __restrict__ bq,
                                                    const float* __restrict__ bk,
                                                    const float* __restrict__ bv,
                                                    const float* __restrict__ bs,
                                                    int layer) {
    __shared__ uint32_t As[2][128 * SA];
    __shared__ uint32_t Bs[2][16 * SB];

    int mat = blockIdx.x >> 1;
    int bn = (blockIdx.x & 1) * 128;
    int bm = blockIdx.y * 128;
    const float* bias = ((mat == 0) ? bq : (mat == 1) ? bk : (mat == 2) ? bv : bs) + layer * DD;
    float* Cm = (mat == 0) ? g_q : (mat == 1) ? g_k : (mat == 2) ? g_v : g_xr;
    const uint32_t* A = g_ht;
    const uint32_t* B = g_wt + (size_t)(layer * 4 + mat) * DD * DD;

    int tid = threadIdx.x;
    int warp = tid >> 5, lane = tid & 31;
    int gid = lane >> 2, tig = lane & 3;
    int warp_m = (warp & 1) * 64;
    int warp_n = (warp >> 1) * 32;

    float acc[4][4][4];
#pragma unroll
    for (int i = 0; i < 4; i++)
#pragma unroll
        for (int j = 0; j < 4; j++)
#pragma unroll
            for (int r = 0; r < 4; r++) acc[i][j][r] = 0.f;

    uint32_t as_base = (uint32_t)__cvta_generic_to_shared(&As[0][0]);
    uint32_t bs_base = (uint32_t)__cvta_generic_to_shared(&Bs[0][0]);

    int a_row = tid >> 2, a_kq = (tid & 3) * 4;
    int b_row = tid >> 5, b_nq = (tid & 31) * 4;

    auto load_tiles = [&](int buf, int k0) {
        cp16(as_base + (uint32_t)(buf * 128 * SA + a_row * SA + a_kq) * 4u,
             &A[(size_t)(bm + a_row) * 256 + k0 + a_kq]);
        cp16(as_base + (uint32_t)(buf * 128 * SA + (a_row + 64) * SA + a_kq) * 4u,
             &A[(size_t)(bm + a_row + 64) * 256 + k0 + a_kq]);
        cp16(bs_base + (uint32_t)(buf * 16 * SB + b_row * SB + b_nq) * 4u,
             &B[(size_t)(k0 + b_row) * 256 + bn + b_nq]);
        cp16(bs_base + (uint32_t)(buf * 16 * SB + (b_row + 8) * SB + b_nq) * 4u,
             &B[(size_t)(k0 + b_row + 8) * 256 + bn + b_nq]);
    };

    load_tiles(0, 0);
    asm volatile("cp.async.commit_group;");

    for (int it = 0; it < 16; it++) {
        int buf = it & 1;
        if (it + 1 < 16) load_tiles(buf ^ 1, (it + 1) * 16);
        asm volatile("cp.async.commit_group;");
        asm volatile("cp.async.wait_group 1;");
        __syncthreads();

        const uint32_t* Ab = &As[buf][0];
        const uint32_t* Bb = &Bs[buf][0];
#pragma unroll
        for (int ks = 0; ks < 16; ks += 8) {
            uint32_t bfr[4][2];
#pragma unroll
            for (int fn = 0; fn < 4; fn++) {
                int n = warp_n + fn * 8 + gid;
                bfr[fn][0] = Bb[(ks + tig) * SB + n];
                bfr[fn][1] = Bb[(ks + tig + 4) * SB + n];
            }
            uint32_t afr[4][4];
#pragma unroll
            for (int fm = 0; fm < 4; fm++) {
                int m = warp_m + fm * 16 + gid;
                afr[fm][0] = Ab[m * SA + ks + tig];
                afr[fm][1] = Ab[(m + 8) * SA + ks + tig];
                afr[fm][2] = Ab[m * SA + ks + tig + 4];
                afr[fm][3] = Ab[(m + 8) * SA + ks + tig + 4];
            }
#pragma unroll
            for (int fm = 0; fm < 4; fm++)
#pragma unroll
                for (int fn = 0; fn < 4; fn++) mma8(acc[fm][fn], afr[fm], bfr[fn]);
        }
        __syncthreads();
    }

#pragma unroll
    for (int fm = 0; fm < 4; fm++) {
        int row = bm + warp_m + fm * 16 + gid;
#pragma unroll
        for (int fn = 0; fn < 4; fn++) {
            int col = bn + warp_n + fn * 8 + tig * 2;
            float b0 = bias[col], b1 = bias[col + 1];
            float2 o0 = make_float2(acc[fm][fn][0] + b0, acc[fm][fn][1] + b1);
            float2 o1 = make_float2(acc[fm][fn][2] + b0, acc[fm][fn][3] + b1);
            *reinterpret_cast<float2*>(&Cm[(size_t)row * 256 + col]) = o0;
            *reinterpret_cast<float2*>(&Cm[(size_t)(row + 8) * 256 + col]) = o1;
        }
    }
}

// ------------------------- fused attention + combine + BN-stats (CSR gather, no atomic scatter) -------------------------
// Warp per dst node, 8 nodes per warp, 512 blocks x 8 warps.
// alpha = q.k + av*(q.We); out = (sum ex*v + (sum ex*av)*We) / sum ex  (per head)
// then beta-gated skip, h write, per-block BN stats -> global atomics.
__global__ __launch_bounds__(256) void attn_combine_kernel(const float* __restrict__ We,
                                                           const float* __restrict__ Wb) {
    __shared__ float sWe[256];
    __shared__ float sWb[768];
    __shared__ float sS[8 * 256];
    __shared__ float sS2[8 * 256];
    int tid = threadIdx.x;
    sWe[tid] = We[tid];
    sWb[tid] = Wb[tid];
    sWb[tid + 256] = Wb[tid + 256];
    sWb[tid + 512] = Wb[tid + 512];
    __syncthreads();
    int warp = tid >> 5, lane = tid & 31;
    int head = lane >> 3, sub = lane & 7;
    int ch = head * 64 + sub * 8;

    float st[8], st2[8];
#pragma unroll
    for (int i = 0; i < 8; i++) { st[i] = 0.f; st2[i] = 0.f; }

    for (int it = 0; it < 8; it++) {
        int n = blockIdx.x * 64 + it * 8 + warp;

        // q row for this node (8 channels per lane)
        float4 q0 = *reinterpret_cast<const float4*>(&g_q[n * 256 + ch]);
        float4 q1 = *reinterpret_cast<const float4*>(&g_q[n * 256 + ch + 4]);
        float qv[8] = {q0.x, q0.y, q0.z, q0.w, q1.x, q1.y, q1.z, q1.w};
        // qWe = q . We within head
        float qwe = 0.f;
#pragma unroll
        for (int i = 0; i < 8; i++) qwe += qv[i] * sWe[ch + i];
        qwe += __shfl_xor_sync(0xffffffffu, qwe, 4);
        qwe += __shfl_xor_sync(0xffffffffu, qwe, 2);
        qwe += __shfl_xor_sync(0xffffffffu, qwe, 1);

        int e0 = g_rowptr[n], e1 = g_rowptr[n + 1];
        float acc[8];
#pragma unroll
        for (int i = 0; i < 8; i++) acc[i] = 0.f;
        float den = 0.f, exav = 0.f;

        for (int j = e0; j < e1; j++) {
            int s = g_esrc[j];
            float av = g_eav[j];
            float4 k0 = *reinterpret_cast<const float4*>(&g_k[s * 256 + ch]);
            float4 k1 = *reinterpret_cast<const float4*>(&g_k[s * 256 + ch + 4]);
            float p = qv[0] * k0.x + qv[1] * k0.y + qv[2] * k0.z + qv[3] * k0.w +
                      qv[4] * k1.x + qv[5] * k1.y + qv[6] * k1.z + qv[7] * k1.w;
            p += __shfl_xor_sync(0xffffffffu, p, 4);
            p += __shfl_xor_sync(0xffffffffu, p, 2);
            p += __shfl_xor_sync(0xffffffffu, p, 1);
            p += av * qwe;
            float ex = expf(p * 0.125f);  // scale = 1/sqrt(64); max-shift cancels in ratio
            float4 v0 = *reinterpret_cast<const float4*>(&g_v[s * 256 + ch]);
            float4 v1 = *reinterpret_cast<const float4*>(&g_v[s * 256 + ch + 4]);
            acc[0] += ex * v0.x; acc[1] += ex * v0.y; acc[2] += ex * v0.z; acc[3] += ex * v0.w;
            acc[4] += ex * v1.x; acc[5] += ex * v1.y; acc[6] += ex * v1.z; acc[7] += ex * v1.w;
            den += ex;
            exav += ex * av;
        }

        float inv = (den > 0.f) ? (1.f / den) : 0.f;  // isolated node -> out = 0
        float ov[8];
#pragma unroll
        for (int i = 0; i < 8; i++) ov[i] = (acc[i] + exav * sWe[ch + i]) * inv;

        // beta-gated skip
        float4 x0 = *reinterpret_cast<const float4*>(&g_xr[n * 256 + ch]);
        float4 x1 = *reinterpret_cast<const float4*>(&g_xr[n * 256 + ch + 4]);
        float xv[8] = {x0.x, x0.y, x0.z, x0.w, x1.x, x1.y, x1.z, x1.w};
        float p = 0.f;
#pragma unroll
        for (int i = 0; i < 8; i++)
            p += ov[i] * sWb[ch + i] + xv[i] * sWb[256 + ch + i] + (ov[i] - xv[i]) * sWb[512 + ch + i];
#pragma unroll
        for (int off = 16; off; off >>= 1) p += __shfl_xor_sync(0xffffffffu, p, off);
        float beta = 1.f / (1.f + expf(-p));
        float r[8];
#pragma unroll
        for (int i = 0; i < 8; i++) {
            r[i] = beta * xv[i] + (1.f - beta) * ov[i];
            st[i] += r[i];
            st2[i] += r[i] * r[i];
        }
        *reinterpret_cast<float4*>(&g_h[n * 256 + ch]) = make_float4(r[0], r[1], r[2], r[3]);
        *reinterpret_cast<float4*>(&g_h[n * 256 + ch + 4]) = make_float4(r[4], r[5], r[6], r[7]);
    }

#pragma unroll
    for (int i = 0; i < 8; i++) {
        sS[warp * 256 + ch + i] = st[i];
        sS2[warp * 256 + ch + i] = st2[i];
    }
    __syncthreads();
    float ts = 0.f, ts2 = 0.f;
#pragma unroll
    for (int w = 0; w < 8; w++) {
        ts += sS[w * 256 + tid];
        ts2 += sS2[w * 256 + tid];
    }
    atomicAdd(&g_colstats[tid], ts);
    atomicAdd(&g_colstats[256 + tid], ts2);
}

// ------------------------- BN apply + ELU (layer 1: also writes tf32 copy) -------------------------
__global__ void bn_apply_l1_kernel(const float* __restrict__ gamma, const float* __restrict__ beta) {
    int i = blockIdx.x * blockDim.x + threadIdx.x;
    if (i >= NN * DD) return;
    int d = i & 255;
    float mu = g_colstats[d] * (1.f / NN);
    float var = g_colstats[256 + d] * (1.f / NN) - mu * mu;
    float y = gamma[d] * (g_h[i] - mu) * rsqrtf(var + BN_EPS) + beta[d];
    float r = y > 0.f ? y : expm1f(y);
    g_h[i] = r;
    g_ht[i] = f2tf32(r);
}

// ------------------------- BN apply + ELU + fused gate (layer 2) -------------------------
__global__ void bn_apply_gate_kernel(const float* __restrict__ gamma, const float* __restrict__ beta,
                                     const int* __restrict__ batch, const float* __restrict__ gW,
                                     const float* __restrict__ gb) {
    __shared__ float sgW[256];
    int tid = threadIdx.x;
    sgW[tid] = gW[tid];
    __syncthreads();
    int warp = tid >> 5, lane = tid & 31;
    int n = blockIdx.x * 8 + warp;
    if (n >= NN) return;
    int ch = lane * 8;
    float p = 0.f;
    float r[8];
#pragma unroll
    for (int i = 0; i < 8; i++) {
        int d = ch + i;
        float mu = g_colstats[d] * (1.f / NN);
        float var = g_colstats[256 + d] * (1.f / NN) - mu * mu;
        float y = gamma[d] * (g_h[n * 256 + d] - mu) * rsqrtf(var + BN_EPS) + beta[d];
        r[i] = y > 0.f ? y : expm1f(y);
        p += r[i] * sgW[d];
    }
    *reinterpret_cast<float4*>(&g_h[n * 256 + ch]) = make_float4(r[0], r[1], r[2], r[3]);
    *reinterpret_cast<float4*>(&g_h[n * 256 + ch + 4]) = make_float4(r[4], r[5], r[6], r[7]);
#pragma unroll
    for (int off = 16; off; off >>= 1) p += __shfl_xor_sync(0xffffffffu, p, off);
    if (lane == 0) {
        float ex = expf(p + gb[0]);
        g_gate[n] = ex;
        atomicAdd(&g_gden[batch[n]], ex);
    }
}

// ------------------------- readout: weighted pooling -------------------------
__global__ void pool_kernel(const int* __restrict__ batch) {
    int i = blockIdx.x * blockDim.x + threadIdx.x;
    if (i >= NN * 64) return;
    int n = i >> 6, c4 = (i & 63) * 4;
    int g = batch[n];
    float w = g_gate[n] / g_gden[g];
    float4 hv = *reinterpret_cast<const float4*>(&g_h[n * 256 + c4]);
    float4 m = make_float4(hv.x * w, hv.y * w, hv.z * w, hv.w * w);
    atomicAdd(reinterpret_cast<float4*>(&g_hG[g * 256 + c4]), m);
}

// ------------------------- decoder -------------------------
__global__ void final_kernel(const float* __restrict__ dW, const float* __restrict__ db,
                             const float* __restrict__ ob, float* __restrict__ out) {
    __shared__ float red[256];
    int g = blockIdx.x, t = threadIdx.x;
    red[t] = g_hG[g * 256 + t] * dW[t];
    __syncthreads();
    for (int s = 128; s > 0; s >>= 1) {
        if (t < s) red[t] += red[t + s];
        __syncthreads();
    }
    if (t == 0) out[g] = red[0] + db[0] + ob[0];
}

// ------------------------- launcher -------------------------
extern "C" void kernel_launch(void* const* d_in, const int* in_sizes, int n_in,
                              void* d_out, int out_size) {
    const float* x     = (const float*)d_in[0];
    const int*   ei    = (const int*)d_in[1];
    const float* ea    = (const float*)d_in[2];
    const int*   batch = (const int*)d_in[3];
    const float* encW  = (const float*)d_in[4];
    const float* encb  = (const float*)d_in[5];
    const float* Wq    = (const float*)d_in[6];
    const float* bq    = (const float*)d_in[7];
    const float* Wk    = (const float*)d_in[8];
    const float* bk    = (const float*)d_in[9];
    const float* Wv    = (const float*)d_in[10];
    const float* bv    = (const float*)d_in[11];
    const float* We    = (const float*)d_in[12];
    const float* Wskip = (const float*)d_in[13];
    const float* bskip = (const float*)d_in[14];
    const float* Wbeta = (const float*)d_in[15];
    const float* bng   = (const float*)d_in[16];
    const float* bnb   = (const float*)d_in[17];
    const float* gW    = (const float*)d_in[18];
    const float* gb    = (const float*)d_in[19];
    const float* dW    = (const float*)d_in[20];
    const float* db    = (const float*)d_in[21];
    const float* ob    = (const float*)d_in[22];
    float* out = (float*)d_out;

    const int* src = ei;        // edge_index[0]
    const int* dst = ei + EE;   // edge_index[1]

    const int TPB = 256;
    const int ND_BLOCKS = (NN * DD) / TPB;

    // one-time prep: tf32 weights, CSR build, readout zero, encoder
    prep_w_kernel<<<dim3(DD * DD / TPB, 8), TPB>>>(Wq, Wk, Wv, Wskip);
    zero_readout_kernel<<<32, TPB>>>();
    zero_cnt_kernel<<<NN / TPB, TPB>>>();
    deg_hist_kernel<<<EE / TPB, TPB>>>(dst);
    scan_kernel<<<1, 1024>>>();
    zero_cnt_kernel<<<NN / TPB, TPB>>>();
    scatter_kernel<<<EE / TPB, TPB>>>(src, dst, ea);
    encoder_kernel<<<ND_BLOCKS, TPB>>>(x, encW, encb);

    for (int l = 0; l < 2; l++) {
        mma_gemm4<<<dim3(8, 256), TPB>>>(bq, bk, bv, bskip, l);
        zero_stats_kernel<<<2, TPB>>>();
        attn_combine_kernel<<<512, TPB>>>(We + l * DD, Wbeta + l * 3 * DD);
        if (l == 0) {
            bn_apply_l1_kernel<<<ND_BLOCKS, TPB>>>(bng, bnb);
        } else {
            bn_apply_gate_kernel<<<NN / 8, TPB>>>(bng + DD, bnb + DD, batch, gW, gb);
        }
    }

    pool_kernel<<<(NN * 64) / TPB, TPB>>>(batch);
    final_kernel<<<GG, TPB>>>(dW, db, ob, out);
}

// round 11
// speedup vs baseline: 1.6507x; 1.0249x over previous
#include <cuda_runtime.h>
#include <math.h>
#include <stdint.h>

#define NN 32768
#define EE 262144
#define DD 256
#define HH 4
#define GG 32
#define BN_EPS 1e-5f

// ------------------------- scratch (device globals) -------------------------
__device__ float g_h[NN * DD];
__device__ uint32_t g_ht[NN * DD];     // tf32-rounded copy of g_h (GEMM A operand)
__device__ uint32_t g_wt[8 * DD * DD]; // tf32 weights: (layer*4 + {q,k,v,skip})
__device__ float g_q[NN * DD];
__device__ float g_k[NN * DD];
__device__ float g_v[NN * DD];
__device__ float g_xr[NN * DD];
__device__ float g_colstats[2 * DD];
__device__ float g_gate[NN];
__device__ float g_gden[GG];
__device__ float g_hG[GG * DD];
// CSR by dst
__device__ int g_rowptr[NN + 1];
__device__ int g_cnt[NN];
__device__ int g_esrc[EE];
__device__ float g_eav[EE];

__device__ __forceinline__ uint32_t f2tf32(float f) {
    uint32_t r;
    asm("cvt.rna.tf32.f32 %0, %1;" : "=r"(r) : "f"(f));
    return r;
}

// ------------------------- small zero kernels -------------------------
__global__ void zero_cnt_kernel() {
    int i = blockIdx.x * blockDim.x + threadIdx.x;
    if (i < NN) g_cnt[i] = 0;
}
__global__ void zero_stats_kernel() {
    int i = blockIdx.x * blockDim.x + threadIdx.x;
    if (i < 2 * DD) g_colstats[i] = 0.f;
}
__global__ void zero_readout_kernel() {
    int i = blockIdx.x * blockDim.x + threadIdx.x;
    if (i < GG * DD) g_hG[i] = 0.f;
    if (i < GG) g_gden[i] = 0.f;
}

// ------------------------- CSR build -------------------------
__global__ void deg_hist_kernel(const int* __restrict__ dst) {
    int e = blockIdx.x * blockDim.x + threadIdx.x;
    if (e < EE) atomicAdd(&g_cnt[dst[e]], 1);
}

__global__ void scan_kernel() {
    __shared__ int swarp[32];
    __shared__ int carry;
    int tid = threadIdx.x;
    int lane = tid & 31, w = tid >> 5;
    if (tid == 0) carry = 0;
    __syncthreads();
    for (int base = 0; base < NN; base += 1024) {
        int x = g_cnt[base + tid];
#pragma unroll
        for (int o = 1; o < 32; o <<= 1) {
            int y = __shfl_up_sync(0xffffffffu, x, o);
            if (lane >= o) x += y;
        }
        if (lane == 31) swarp[w] = x;
        __syncthreads();
        if (w == 0) {
            int y = swarp[lane];
#pragma unroll
            for (int o = 1; o < 32; o <<= 1) {
                int z = __shfl_up_sync(0xffffffffu, y, o);
                if (lane >= o) y += z;
            }
            swarp[lane] = y;
        }
        __syncthreads();
        int incl = x + (w > 0 ? swarp[w - 1] : 0) + carry;
        g_rowptr[base + tid + 1] = incl;
        __syncthreads();
        if (tid == 1023) carry = incl;
        __syncthreads();
    }
    if (tid == 0) g_rowptr[0] = 0;
}

__global__ void scatter_kernel(const int* __restrict__ src, const int* __restrict__ dst,
                               const float* __restrict__ ea) {
    int e = blockIdx.x * blockDim.x + threadIdx.x;
    if (e >= EE) return;
    int d = dst[e];
    int pos = g_rowptr[d] + atomicAdd(&g_cnt[d], 1);
    g_esrc[pos] = src[e];
    g_eav[pos] = ea[e];
}

// ------------------------- weight prep -------------------------
__global__ void prep_w_kernel(const float* __restrict__ Wq, const float* __restrict__ Wk,
                              const float* __restrict__ Wv, const float* __restrict__ Ws) {
    int m = blockIdx.y;            // 0..7 : layer*4 + which
    int i = blockIdx.x * blockDim.x + threadIdx.x;
    int l = m >> 2, w = m & 3;
    const float* S = (w == 0) ? Wq : (w == 1) ? Wk : (w == 2) ? Wv : Ws;
    g_wt[m * DD * DD + i] = f2tf32(S[l * DD * DD + i]);
}

// ------------------------- encoder -------------------------
__global__ void encoder_kernel(const float* __restrict__ x,
                               const float* __restrict__ W,
                               const float* __restrict__ b) {
    int i = blockIdx.x * blockDim.x + threadIdx.x;
    if (i >= NN * DD) return;
    int n = i >> 8, d = i & 255;
    float h = x[n * 2] * W[d] + x[n * 2 + 1] * W[DD + d] + b[d];
    g_h[i] = h;
    g_ht[i] = f2tf32(h);
}

// ------------------------- TF32 mma.sync GEMM: all 4 matrices in one launch -------------------------
#define SA 20
#define SB 136

__device__ __forceinline__ void cp16(uint32_t s, const void* g) {
    asm volatile("cp.async.ca.shared.global [%0], [%1], 16;" :: "r"(s), "l"(g));
}

__device__ __forceinline__ void mma8(float* c, const uint32_t* a, const uint32_t* b) {
    asm volatile(
        "mma.sync.aligned.m16n8k8.row.col.f32.tf32.tf32.f32 "
        "{%0,%1,%2,%3}, {%4,%5,%6,%7}, {%8,%9}, {%0,%1,%2,%3};"
        : "+f"(c[0]), "+f"(c[1]), "+f"(c[2]), "+f"(c[3])
        : "r"(a[0]), "r"(a[1]), "r"(a[2]), "r"(a[3]), "r"(b[0]), "r"(b[1]));
}

__global__ __launch_bounds__(256, 2) void mma_gemm4(const float* __restrict__ bq,
                                                    const float* __restrict__ bk,
                                                    const float* __restrict__ bv,
                                                    const float* __restrict__ bs,
                                                    int layer) {
    __shared__ uint32_t As[2][128 * SA];
    __shared__ uint32_t Bs[2][16 * SB];

    int mat = blockIdx.x >> 1;
    int bn = (blockIdx.x & 1) * 128;
    int bm = blockIdx.y * 128;
    const float* bias = ((mat == 0) ? bq : (mat == 1) ? bk : (mat == 2) ? bv : bs) + layer * DD;
    float* Cm = (mat == 0) ? g_q : (mat == 1) ? g_k : (mat == 2) ? g_v : g_xr;
    const uint32_t* A = g_ht;
    const uint32_t* B = g_wt + (size_t)(layer * 4 + mat) * DD * DD;

    int tid = threadIdx.x;
    int warp = tid >> 5, lane = tid & 31;
    int gid = lane >> 2, tig = lane & 3;
    int warp_m = (warp & 1) * 64;
    int warp_n = (warp >> 1) * 32;

    float acc[4][4][4];
#pragma unroll
    for (int i = 0; i < 4; i++)
#pragma unroll
        for (int j = 0; j < 4; j++)
#pragma unroll
            for (int r = 0; r < 4; r++) acc[i][j][r] = 0.f;

    uint32_t as_base = (uint32_t)__cvta_generic_to_shared(&As[0][0]);
    uint32_t bs_base = (uint32_t)__cvta_generic_to_shared(&Bs[0][0]);

    int a_row = tid >> 2, a_kq = (tid & 3) * 4;
    int b_row = tid >> 5, b_nq = (tid & 31) * 4;

    auto load_tiles = [&](int buf, int k0) {
        cp16(as_base + (uint32_t)(buf * 128 * SA + a_row * SA + a_kq) * 4u,
             &A[(size_t)(bm + a_row) * 256 + k0 + a_kq]);
        cp16(as_base + (uint32_t)(buf * 128 * SA + (a_row + 64) * SA + a_kq) * 4u,
             &A[(size_t)(bm + a_row + 64) * 256 + k0 + a_kq]);
        cp16(bs_base + (uint32_t)(buf * 16 * SB + b_row * SB + b_nq) * 4u,
             &B[(size_t)(k0 + b_row) * 256 + bn + b_nq]);
        cp16(bs_base + (uint32_t)(buf * 16 * SB + (b_row + 8) * SB + b_nq) * 4u,
             &B[(size_t)(k0 + b_row + 8) * 256 + bn + b_nq]);
    };

    load_tiles(0, 0);
    asm volatile("cp.async.commit_group;");

    for (int it = 0; it < 16; it++) {
        int buf = it & 1;
        if (it + 1 < 16) load_tiles(buf ^ 1, (it + 1) * 16);
        asm volatile("cp.async.commit_group;");
        asm volatile("cp.async.wait_group 1;");
        __syncthreads();

        const uint32_t* Ab = &As[buf][0];
        const uint32_t* Bb = &Bs[buf][0];
#pragma unroll
        for (int ks = 0; ks < 16; ks += 8) {
            uint32_t bfr[4][2];
#pragma unroll
            for (int fn = 0; fn < 4; fn++) {
                int n = warp_n + fn * 8 + gid;
                bfr[fn][0] = Bb[(ks + tig) * SB + n];
                bfr[fn][1] = Bb[(ks + tig + 4) * SB + n];
            }
            uint32_t afr[4][4];
#pragma unroll
            for (int fm = 0; fm < 4; fm++) {
                int m = warp_m + fm * 16 + gid;
                afr[fm][0] = Ab[m * SA + ks + tig];
                afr[fm][1] = Ab[(m + 8) * SA + ks + tig];
                afr[fm][2] = Ab[m * SA + ks + tig + 4];
                afr[fm][3] = Ab[(m + 8) * SA + ks + tig + 4];
            }
#pragma unroll
            for (int fm = 0; fm < 4; fm++)
#pragma unroll
                for (int fn = 0; fn < 4; fn++) mma8(acc[fm][fn], afr[fm], bfr[fn]);
        }
        __syncthreads();
    }

#pragma unroll
    for (int fm = 0; fm < 4; fm++) {
        int row = bm + warp_m + fm * 16 + gid;
#pragma unroll
        for (int fn = 0; fn < 4; fn++) {
            int col = bn + warp_n + fn * 8 + tig * 2;
            float b0 = bias[col], b1 = bias[col + 1];
            float2 o0 = make_float2(acc[fm][fn][0] + b0, acc[fm][fn][1] + b1);
            float2 o1 = make_float2(acc[fm][fn][2] + b0, acc[fm][fn][3] + b1);
            *reinterpret_cast<float2*>(&Cm[(size_t)row * 256 + col]) = o0;
            *reinterpret_cast<float2*>(&Cm[(size_t)(row + 8) * 256 + col]) = o1;
        }
    }
}

// ------------------------- fused attention + combine + BN-stats (pipelined CSR gather) ----------
__global__ __launch_bounds__(256) void attn_combine_kernel(const float* __restrict__ We,
                                                           const float* __restrict__ Wb) {
    __shared__ float sWe[256];
    __shared__ float sWb[768];
    __shared__ float sS[8 * 256];
    __shared__ float sS2[8 * 256];
    int tid = threadIdx.x;
    sWe[tid] = We[tid];
    sWb[tid] = Wb[tid];
    sWb[tid + 256] = Wb[tid + 256];
    sWb[tid + 512] = Wb[tid + 512];
    __syncthreads();
    int warp = tid >> 5, lane = tid & 31;
    int head = lane >> 3;
    int ch = head * 64 + (lane & 7) * 8;

    float st[8], st2[8];
#pragma unroll
    for (int i = 0; i < 8; i++) { st[i] = 0.f; st2[i] = 0.f; }

    for (int it = 0; it < 8; it++) {
        int n = blockIdx.x * 64 + it * 8 + warp;

        float4 q0 = *reinterpret_cast<const float4*>(&g_q[n * 256 + ch]);
        float4 q1 = *reinterpret_cast<const float4*>(&g_q[n * 256 + ch + 4]);
        float qv[8] = {q0.x, q0.y, q0.z, q0.w, q1.x, q1.y, q1.z, q1.w};
        float qwe = 0.f;
#pragma unroll
        for (int i = 0; i < 8; i++) qwe += qv[i] * sWe[ch + i];
        qwe += __shfl_xor_sync(0xffffffffu, qwe, 4);
        qwe += __shfl_xor_sync(0xffffffffu, qwe, 2);
        qwe += __shfl_xor_sync(0xffffffffu, qwe, 1);

        int e0 = g_rowptr[n], e1 = g_rowptr[n + 1];
        float acc[8];
#pragma unroll
        for (int i = 0; i < 8; i++) acc[i] = 0.f;
        float den = 0.f, exav = 0.f;

        if (e0 < e1) {
            int s = g_esrc[e0];
            float av = g_eav[e0];
            float4 k0 = *reinterpret_cast<const float4*>(&g_k[s * 256 + ch]);
            float4 k1 = *reinterpret_cast<const float4*>(&g_k[s * 256 + ch + 4]);
            float4 v0 = *reinterpret_cast<const float4*>(&g_v[s * 256 + ch]);
            float4 v1 = *reinterpret_cast<const float4*>(&g_v[s * 256 + ch + 4]);
            for (int j = e0; j < e1; j++) {
                // prefetch next edge before this edge's dependent chain
                float av2 = 0.f;
                float4 nk0, nk1, nv0, nv1;
                bool more = (j + 1 < e1);
                if (more) {
                    int s2 = g_esrc[j + 1];
                    av2 = g_eav[j + 1];
                    nk0 = *reinterpret_cast<const float4*>(&g_k[s2 * 256 + ch]);
                    nk1 = *reinterpret_cast<const float4*>(&g_k[s2 * 256 + ch + 4]);
                    nv0 = *reinterpret_cast<const float4*>(&g_v[s2 * 256 + ch]);
                    nv1 = *reinterpret_cast<const float4*>(&g_v[s2 * 256 + ch + 4]);
                }
                float p = qv[0] * k0.x + qv[1] * k0.y + qv[2] * k0.z + qv[3] * k0.w +
                          qv[4] * k1.x + qv[5] * k1.y + qv[6] * k1.z + qv[7] * k1.w;
                p += __shfl_xor_sync(0xffffffffu, p, 4);
                p += __shfl_xor_sync(0xffffffffu, p, 2);
                p += __shfl_xor_sync(0xffffffffu, p, 1);
                p += av * qwe;
                float ex = expf(p * 0.125f);  // scale=1/sqrt(64); max-shift cancels in ratio
                acc[0] += ex * v0.x; acc[1] += ex * v0.y; acc[2] += ex * v0.z; acc[3] += ex * v0.w;
                acc[4] += ex * v1.x; acc[5] += ex * v1.y; acc[6] += ex * v1.z; acc[7] += ex * v1.w;
                den += ex;
                exav += ex * av;
                if (more) { av = av2; k0 = nk0; k1 = nk1; v0 = nv0; v1 = nv1; }
            }
        }

        float inv = (den > 0.f) ? (1.f / den) : 0.f;  // isolated node -> out = 0
        float ov[8];
#pragma unroll
        for (int i = 0; i < 8; i++) ov[i] = (acc[i] + exav * sWe[ch + i]) * inv;

        float4 x0 = *reinterpret_cast<const float4*>(&g_xr[n * 256 + ch]);
        float4 x1 = *reinterpret_cast<const float4*>(&g_xr[n * 256 + ch + 4]);
        float xv[8] = {x0.x, x0.y, x0.z, x0.w, x1.x, x1.y, x1.z, x1.w};
        float p = 0.f;
#pragma unroll
        for (int i = 0; i < 8; i++)
            p += ov[i] * sWb[ch + i] + xv[i] * sWb[256 + ch + i] + (ov[i] - xv[i]) * sWb[512 + ch + i];
#pragma unroll
        for (int off = 16; off; off >>= 1) p += __shfl_xor_sync(0xffffffffu, p, off);
        float beta = 1.f / (1.f + expf(-p));
        float r[8];
#pragma unroll
        for (int i = 0; i < 8; i++) {
            r[i] = beta * xv[i] + (1.f - beta) * ov[i];
            st[i] += r[i];
            st2[i] += r[i] * r[i];
        }
        *reinterpret_cast<float4*>(&g_h[n * 256 + ch]) = make_float4(r[0], r[1], r[2], r[3]);
        *reinterpret_cast<float4*>(&g_h[n * 256 + ch + 4]) = make_float4(r[4], r[5], r[6], r[7]);
    }

#pragma unroll
    for (int i = 0; i < 8; i++) {
        sS[warp * 256 + ch + i] = st[i];
        sS2[warp * 256 + ch + i] = st2[i];
    }
    __syncthreads();
    float ts = 0.f, ts2 = 0.f;
#pragma unroll
    for (int w = 0; w < 8; w++) {
        ts += sS[w * 256 + tid];
        ts2 += sS2[w * 256 + tid];
    }
    atomicAdd(&g_colstats[tid], ts);
    atomicAdd(&g_colstats[256 + tid], ts2);
}

// ------------------------- BN apply + ELU (layer 1) -------------------------
__global__ void bn_apply_l1_kernel(const float* __restrict__ gamma, const float* __restrict__ beta) {
    int i = blockIdx.x * blockDim.x + threadIdx.x;
    if (i >= NN * DD) return;
    int d = i & 255;
    float mu = g_colstats[d] * (1.f / NN);
    float var = g_colstats[256 + d] * (1.f / NN) - mu * mu;
    float y = gamma[d] * (g_h[i] - mu) * rsqrtf(var + BN_EPS) + beta[d];
    float r = y > 0.f ? y : expm1f(y);
    g_h[i] = r;
    g_ht[i] = f2tf32(r);
}

// ------------------------- BN apply + ELU + gate (layer 2) -------------------------
__global__ void bn_apply_gate_kernel(const float* __restrict__ gamma, const float* __restrict__ beta,
                                     const int* __restrict__ batch, const float* __restrict__ gW,
                                     const float* __restrict__ gb) {
    __shared__ float sgW[256];
    int tid = threadIdx.x;
    sgW[tid] = gW[tid];
    __syncthreads();
    int warp = tid >> 5, lane = tid & 31;
    int n = blockIdx.x * 8 + warp;
    if (n >= NN) return;
    int ch = lane * 8;
    float p = 0.f;
    float r[8];
#pragma unroll
    for (int i = 0; i < 8; i++) {
        int d = ch + i;
        float mu = g_colstats[d] * (1.f / NN);
        float var = g_colstats[256 + d] * (1.f / NN) - mu * mu;
        float y = gamma[d] * (g_h[n * 256 + d] - mu) * rsqrtf(var + BN_EPS) + beta[d];
        r[i] = y > 0.f ? y : expm1f(y);
        p += r[i] * sgW[d];
    }
    *reinterpret_cast<float4*>(&g_h[n * 256 + ch]) = make_float4(r[0], r[1], r[2], r[3]);
    *reinterpret_cast<float4*>(&g_h[n * 256 + ch + 4]) = make_float4(r[4], r[5], r[6], r[7]);
#pragma unroll
    for (int off = 16; off; off >>= 1) p += __shfl_xor_sync(0xffffffffu, p, off);
    if (lane == 0) {
        float ex = expf(p + gb[0]);
        g_gate[n] = ex;
        atomicAdd(&g_gden[batch[n]], ex);
    }
}

// ------------------------- readout: segment-aware pooling (batch is sorted) -------------------------
// 128 blocks; block b handles nodes [b*256, b*256+256). Thread t = channel t.
// Per-node weights staged in smem; register accumulate, flush on graph-id change.
__global__ __launch_bounds__(256) void pool_seg_kernel(const int* __restrict__ batch) {
    __shared__ float sw[256];
    __shared__ int sbt[256];
    int tid = threadIdx.x;
    int n0 = blockIdx.x * 256;
    {
        int n = n0 + tid;
        int g = batch[n];
        sbt[tid] = g;
        sw[tid] = g_gate[n] / g_gden[g];
    }
    __syncthreads();
    float acc = 0.f;
    int curg = sbt[0];
    for (int i = 0; i < 256; i++) {
        int g = sbt[i];
        if (g != curg) {
            atomicAdd(&g_hG[curg * 256 + tid], acc);
            acc = 0.f;
            curg = g;
        }
        acc += sw[i] * g_h[(n0 + i) * 256 + tid];
    }
    atomicAdd(&g_hG[curg * 256 + tid], acc);
}

__global__ void final_kernel(const float* __restrict__ dW, const float* __restrict__ db,
                             const float* __restrict__ ob, float* __restrict__ out) {
    __shared__ float red[256];
    int g = blockIdx.x, t = threadIdx.x;
    red[t] = g_hG[g * 256 + t] * dW[t];
    __syncthreads();
    for (int s = 128; s > 0; s >>= 1) {
        if (t < s) red[t] += red[t + s];
        __syncthreads();
    }
    if (t == 0) out[g] = red[0] + db[0] + ob[0];
}

// ------------------------- launcher -------------------------
extern "C" void kernel_launch(void* const* d_in, const int* in_sizes, int n_in,
                              void* d_out, int out_size) {
    const float* x     = (const float*)d_in[0];
    const int*   ei    = (const int*)d_in[1];
    const float* ea    = (const float*)d_in[2];
    const int*   batch = (const int*)d_in[3];
    const float* encW  = (const float*)d_in[4];
    const float* encb  = (const float*)d_in[5];
    const float* Wq    = (const float*)d_in[6];
    const float* bq    = (const float*)d_in[7];
    const float* Wk    = (const float*)d_in[8];
    const float* bk    = (const float*)d_in[9];
    const float* Wv    = (const float*)d_in[10];
    const float* bv    = (const float*)d_in[11];
    const float* We    = (const float*)d_in[12];
    const float* Wskip = (const float*)d_in[13];
    const float* bskip = (const float*)d_in[14];
    const float* Wbeta = (const float*)d_in[15];
    const float* bng   = (const float*)d_in[16];
    const float* bnb   = (const float*)d_in[17];
    const float* gW    = (const float*)d_in[18];
    const float* gb    = (const float*)d_in[19];
    const float* dW    = (const float*)d_in[20];
    const float* db    = (const float*)d_in[21];
    const float* ob    = (const float*)d_in[22];
    float* out = (float*)d_out;

    const int* src = ei;
    const int* dst = ei + EE;

    const int TPB = 256;
    const int ND_BLOCKS = (NN * DD) / TPB;

    prep_w_kernel<<<dim3(DD * DD / TPB, 8), TPB>>>(Wq, Wk, Wv, Wskip);
    zero_readout_kernel<<<32, TPB>>>();
    zero_cnt_kernel<<<NN / TPB, TPB>>>();
    deg_hist_kernel<<<EE / TPB, TPB>>>(dst);
    scan_kernel<<<1, 1024>>>();
    zero_cnt_kernel<<<NN / TPB, TPB>>>();
    scatter_kernel<<<EE / TPB, TPB>>>(src, dst, ea);
    encoder_kernel<<<ND_BLOCKS, TPB>>>(x, encW, encb);

    for (int l = 0; l < 2; l++) {
        mma_gemm4<<<dim3(8, 256), TPB>>>(bq, bk, bv, bskip, l);
        zero_stats_kernel<<<2, TPB>>>();
        attn_combine_kernel<<<512, TPB>>>(We + l * DD, Wbeta + l * 3 * DD);
        if (l == 0) {
            bn_apply_l1_kernel<<<ND_BLOCKS, TPB>>>(bng, bnb);
        } else {
            bn_apply_gate_kernel<<<NN / 8, TPB>>>(bng + DD, bnb + DD, batch, gW, gb);
        }
    }

    pool_seg_kernel<<<NN / 256, TPB>>>(batch);
    final_kernel<<<GG, TPB>>>(dW, db, ob, out);
}

// round 12
// speedup vs baseline: 1.7401x; 1.0541x over previous
#include <cuda_runtime.h>
#include <math.h>
#include <stdint.h>

#define NN 32768
#define EE 262144
#define DD 256
#define HH 4
#define GG 32
#define BN_EPS 1e-5f

// ------------------------- scratch (device globals) -------------------------
__device__ float g_h[NN * DD];
__device__ uint32_t g_ht[NN * DD];     // tf32 copy of g_h, PERMUTED to A-fragment order
__device__ uint32_t g_wt[8 * DD * DD]; // tf32 weights, PERMUTED to B-fragment order
__device__ float g_q[NN * DD];
__device__ float g_k[NN * DD];
__device__ float g_v[NN * DD];
__device__ float g_xr[NN * DD];
__device__ float g_colstats[2 * DD];
__device__ float g_gate[NN];
__device__ float g_gden[GG];
__device__ float g_hG[GG * DD];
// CSR by dst
__device__ int g_rowptr[NN + 1];
__device__ int g_cnt[NN];
__device__ int g_esrc[EE];
__device__ float g_eav[EE];

__device__ __forceinline__ uint32_t f2tf32(float f) {
    uint32_t r;
    asm("cvt.rna.tf32.f32 %0, %1;" : "=r"(r) : "f"(f));
    return r;
}

// A-fragment permutation: for 16-row x 8-col blocks, thread quad {(g,t),(g+8,t),(g,t+4),(g+8,t+4)}
// stored contiguously. index = ((rg*32 + kb)*32 + lane)*4 + elem.
__device__ __forceinline__ int permA(int n, int d) {
    int rg = n >> 4, kb = d >> 3;
    int lane = (n & 7) * 4 + (d & 3);
    int elem = ((n >> 3) & 1) + ((d >> 2) & 1) * 2;
    return ((rg * 32 + kb) * 32 + lane) * 4 + elem;
}

// ------------------------- small zero kernels -------------------------
__global__ void zero_cnt_kernel() {
    int i = blockIdx.x * blockDim.x + threadIdx.x;
    if (i < NN) g_cnt[i] = 0;
}
__global__ void zero_stats_kernel() {
    int i = blockIdx.x * blockDim.x + threadIdx.x;
    if (i < 2 * DD) g_colstats[i] = 0.f;
}
__global__ void zero_readout_kernel() {
    int i = blockIdx.x * blockDim.x + threadIdx.x;
    if (i < GG * DD) g_hG[i] = 0.f;
    if (i < GG) g_gden[i] = 0.f;
}

// ------------------------- CSR build -------------------------
__global__ void deg_hist_kernel(const int* __restrict__ dst) {
    int e = blockIdx.x * blockDim.x + threadIdx.x;
    if (e < EE) atomicAdd(&g_cnt[dst[e]], 1);
}

__global__ void scan_kernel() {
    __shared__ int swarp[32];
    __shared__ int carry;
    int tid = threadIdx.x;
    int lane = tid & 31, w = tid >> 5;
    if (tid == 0) carry = 0;
    __syncthreads();
    for (int base = 0; base < NN; base += 1024) {
        int x = g_cnt[base + tid];
#pragma unroll
        for (int o = 1; o < 32; o <<= 1) {
            int y = __shfl_up_sync(0xffffffffu, x, o);
            if (lane >= o) x += y;
        }
        if (lane == 31) swarp[w] = x;
        __syncthreads();
        if (w == 0) {
            int y = swarp[lane];
#pragma unroll
            for (int o = 1; o < 32; o <<= 1) {
                int z = __shfl_up_sync(0xffffffffu, y, o);
                if (lane >= o) y += z;
            }
            swarp[lane] = y;
        }
        __syncthreads();
        int incl = x + (w > 0 ? swarp[w - 1] : 0) + carry;
        g_rowptr[base + tid + 1] = incl;
        __syncthreads();
        if (tid == 1023) carry = incl;
        __syncthreads();
    }
    if (tid == 0) g_rowptr[0] = 0;
}

__global__ void scatter_kernel(const int* __restrict__ src, const int* __restrict__ dst,
                               const float* __restrict__ ea) {
    int e = blockIdx.x * blockDim.x + threadIdx.x;
    if (e >= EE) return;
    int d = dst[e];
    int pos = g_rowptr[d] + atomicAdd(&g_cnt[d], 1);
    g_esrc[pos] = src[e];
    g_eav[pos] = ea[e];
}

// ------------------------- weight prep: tf32 + B-fragment permutation -------------------------
// Layout per mat: 32 k8-blocks x 8 n32-blocks x [2 pairblocks x 32 lanes x 4 floats].
// Lane quad pair p holds {B[k+tig][n+fn*8+gid], B[k+tig+4][n+fn*8+gid]} for fn = 2p, 2p+1.
__global__ void prep_w_kernel(const float* __restrict__ Wq, const float* __restrict__ Wk,
                              const float* __restrict__ Wv, const float* __restrict__ Ws) {
    int m = blockIdx.y;            // 0..7 : layer*4 + which
    int i = blockIdx.x * blockDim.x + threadIdx.x;   // 0..65535
    int l = m >> 2, w = m & 3;
    const float* S = ((w == 0) ? Wq : (w == 1) ? Wk : (w == 2) ? Wv : Ws) + (size_t)l * DD * DD;
    int kb = i >> 11;
    int rem = i & 2047;
    int nb = rem >> 8;
    int o = rem & 255;
    int pairidx = (o >> 7) & 1;
    int lq = (o >> 2) & 31;
    int e = o & 3;
    int fn = pairidx * 2 + (e >> 1);
    int half = e & 1;
    int gid = lq >> 2, tig = lq & 3;
    int k = kb * 8 + tig + half * 4;
    int n = nb * 32 + fn * 8 + gid;
    g_wt[(size_t)m * 65536 + i] = f2tf32(S[k * 256 + n]);
}

// ------------------------- encoder (writes permuted tf32 copy) -------------------------
__global__ void encoder_kernel(const float* __restrict__ x,
                               const float* __restrict__ W,
                               const float* __restrict__ b) {
    int i = blockIdx.x * blockDim.x + threadIdx.x;
    if (i >= NN * DD) return;
    int n = i >> 8, d = i & 255;
    float h = x[n * 2] * W[d] + x[n * 2 + 1] * W[DD + d] + b[d];
    g_h[i] = h;
    g_ht[permA(n, d)] = f2tf32(h);
}

// ------------------------- TF32 mma.sync GEMM, LDS.128 fragment loads -------------------------
__device__ __forceinline__ void cp16(uint32_t s, const void* g) {
    asm volatile("cp.async.ca.shared.global [%0], [%1], 16;" :: "r"(s), "l"(g));
}

__device__ __forceinline__ void mma8(float* c, const uint32_t* a, const uint32_t* b) {
    asm volatile(
        "mma.sync.aligned.m16n8k8.row.col.f32.tf32.tf32.f32 "
        "{%0,%1,%2,%3}, {%4,%5,%6,%7}, {%8,%9}, {%0,%1,%2,%3};"
        : "+f"(c[0]), "+f"(c[1]), "+f"(c[2]), "+f"(c[3])
        : "r"(a[0]), "r"(a[1]), "r"(a[2]), "r"(a[3]), "r"(b[0]), "r"(b[1]));
}

__global__ __launch_bounds__(256, 2) void mma_gemm4(const float* __restrict__ bq,
                                                    const float* __restrict__ bk,
                                                    const float* __restrict__ bv,
                                                    const float* __restrict__ bs,
                                                    int layer) {
    __shared__ uint32_t As[2][2048];  // [rg 8][kb 2][128]
    __shared__ uint32_t Bs[2][2048];  // [kb 2][nb 4][256]

    int mat = blockIdx.x >> 1;
    int bn = (blockIdx.x & 1) * 128;
    int bm = blockIdx.y * 128;
    const float* bias = ((mat == 0) ? bq : (mat == 1) ? bk : (mat == 2) ? bv : bs) + layer * DD;
    float* Cm = (mat == 0) ? g_q : (mat == 1) ? g_k : (mat == 2) ? g_v : g_xr;
    const uint32_t* A = g_ht;
    const uint32_t* B = g_wt + (size_t)(layer * 4 + mat) * 65536;

    int tid = threadIdx.x;
    int warp = tid >> 5, lane = tid & 31;
    int gid = lane >> 2, tig = lane & 3;
    int warp_m = (warp & 1) * 64;
    int warp_n = (warp >> 1) * 32;
    int rg_w = (warp & 1) * 4;   // A row-group base for this warp
    int nb_w = warp >> 1;        // B n32-block for this warp
    int rgbase = bm >> 4;
    int nbbase = bn >> 5;

    float acc[4][4][4];
#pragma unroll
    for (int i = 0; i < 4; i++)
#pragma unroll
        for (int j = 0; j < 4; j++)
#pragma unroll
            for (int r = 0; r < 4; r++) acc[i][j][r] = 0.f;

    uint32_t as_base = (uint32_t)__cvta_generic_to_shared(&As[0][0]);
    uint32_t bs_base = (uint32_t)__cvta_generic_to_shared(&Bs[0][0]);

    auto load_tiles = [&](int buf, int k0) {
        int kb0 = k0 >> 3;
#pragma unroll
        for (int i = 0; i < 2; i++) {
            int slot = tid + i * 256;                 // 0..511
            int rg_i = slot >> 6, kb_i = (slot >> 5) & 1, ch = slot & 31;
            cp16(as_base + (uint32_t)(buf * 2048 + (rg_i * 2 + kb_i) * 128 + ch * 4) * 4u,
                 &A[(size_t)((rgbase + rg_i) * 32 + kb0 + kb_i) * 128 + ch * 4]);
            int kb_j = slot >> 8, nb_j = (slot >> 6) & 3, ch2 = slot & 63;
            cp16(bs_base + (uint32_t)(buf * 2048 + (kb_j * 4 + nb_j) * 256 + ch2 * 4) * 4u,
                 &B[(size_t)((kb0 + kb_j) * 8 + nbbase + nb_j) * 256 + ch2 * 4]);
        }
    };

    load_tiles(0, 0);
    asm volatile("cp.async.commit_group;");

    for (int it = 0; it < 16; it++) {
        int buf = it & 1;
        if (it + 1 < 16) load_tiles(buf ^ 1, (it + 1) * 16);
        asm volatile("cp.async.commit_group;");
        asm volatile("cp.async.wait_group 1;");
        __syncthreads();

#pragma unroll
        for (int ksb = 0; ksb < 2; ksb++) {
            const uint4* bp = reinterpret_cast<const uint4*>(
                &Bs[buf][(ksb * 4 + nb_w) * 256 + lane * 4]);
            uint4 b01 = bp[0];
            uint4 b23 = bp[32];   // +128 uint32 = +32 uint4
            uint32_t bfr[4][2] = {{b01.x, b01.y}, {b01.z, b01.w},
                                  {b23.x, b23.y}, {b23.z, b23.w}};
#pragma unroll
            for (int fm = 0; fm < 4; fm++) {
                uint4 a = *reinterpret_cast<const uint4*>(
                    &As[buf][((rg_w + fm) * 2 + ksb) * 128 + lane * 4]);
                uint32_t afr[4] = {a.x, a.y, a.z, a.w};
#pragma unroll
                for (int fn = 0; fn < 4; fn++) mma8(acc[fm][fn], afr, bfr[fn]);
            }
        }
        __syncthreads();
    }

#pragma unroll
    for (int fm = 0; fm < 4; fm++) {
        int row = bm + warp_m + fm * 16 + gid;
#pragma unroll
        for (int fn = 0; fn < 4; fn++) {
            int col = bn + warp_n + fn * 8 + tig * 2;
            float b0 = bias[col], b1 = bias[col + 1];
            float2 o0 = make_float2(acc[fm][fn][0] + b0, acc[fm][fn][1] + b1);
            float2 o1 = make_float2(acc[fm][fn][2] + b0, acc[fm][fn][3] + b1);
            *reinterpret_cast<float2*>(&Cm[(size_t)row * 256 + col]) = o0;
            *reinterpret_cast<float2*>(&Cm[(size_t)(row + 8) * 256 + col]) = o1;
        }
    }
}

// ------------------------- fused attention + combine + BN-stats (2-edge unrolled gather) ----------
__global__ __launch_bounds__(256) void attn_combine_kernel(const float* __restrict__ We,
                                                           const float* __restrict__ Wb) {
    __shared__ float sWe[256];
    __shared__ float sWb[768];
    __shared__ float sS[8 * 256];
    __shared__ float sS2[8 * 256];
    int tid = threadIdx.x;
    sWe[tid] = We[tid];
    sWb[tid] = Wb[tid];
    sWb[tid + 256] = Wb[tid + 256];
    sWb[tid + 512] = Wb[tid + 512];
    __syncthreads();
    int warp = tid >> 5, lane = tid & 31;
    int head = lane >> 3;
    int ch = head * 64 + (lane & 7) * 8;

    float st[8], st2[8];
#pragma unroll
    for (int i = 0; i < 8; i++) { st[i] = 0.f; st2[i] = 0.f; }

    for (int it = 0; it < 8; it++) {
        int n = blockIdx.x * 64 + it * 8 + warp;

        float4 q0 = *reinterpret_cast<const float4*>(&g_q[n * 256 + ch]);
        float4 q1 = *reinterpret_cast<const float4*>(&g_q[n * 256 + ch + 4]);
        float qv[8] = {q0.x, q0.y, q0.z, q0.w, q1.x, q1.y, q1.z, q1.w};
        float qwe = 0.f;
#pragma unroll
        for (int i = 0; i < 8; i++) qwe += qv[i] * sWe[ch + i];
        qwe += __shfl_xor_sync(0xffffffffu, qwe, 4);
        qwe += __shfl_xor_sync(0xffffffffu, qwe, 2);
        qwe += __shfl_xor_sync(0xffffffffu, qwe, 1);

        int e0 = g_rowptr[n], e1 = g_rowptr[n + 1];
        float acc[8];
#pragma unroll
        for (int i = 0; i < 8; i++) acc[i] = 0.f;
        float den = 0.f, exav = 0.f;

        int j = e0;
        // unroll by 2: two independent load/dot/shfl/exp chains in flight
        for (; j + 1 < e1; j += 2) {
            int sA = g_esrc[j], sB = g_esrc[j + 1];
            float avA = g_eav[j], avB = g_eav[j + 1];
            float4 ka0 = *reinterpret_cast<const float4*>(&g_k[sA * 256 + ch]);
            float4 ka1 = *reinterpret_cast<const float4*>(&g_k[sA * 256 + ch + 4]);
            float4 kb0 = *reinterpret_cast<const float4*>(&g_k[sB * 256 + ch]);
            float4 kb1 = *reinterpret_cast<const float4*>(&g_k[sB * 256 + ch + 4]);
            float4 va0 = *reinterpret_cast<const float4*>(&g_v[sA * 256 + ch]);
            float4 va1 = *reinterpret_cast<const float4*>(&g_v[sA * 256 + ch + 4]);
            float4 vb0 = *reinterpret_cast<const float4*>(&g_v[sB * 256 + ch]);
            float4 vb1 = *reinterpret_cast<const float4*>(&g_v[sB * 256 + ch + 4]);
            float pA = qv[0] * ka0.x + qv[1] * ka0.y + qv[2] * ka0.z + qv[3] * ka0.w +
                       qv[4] * ka1.x + qv[5] * ka1.y + qv[6] * ka1.z + qv[7] * ka1.w;
            float pB = qv[0] * kb0.x + qv[1] * kb0.y + qv[2] * kb0.z + qv[3] * kb0.w +
                       qv[4] * kb1.x + qv[5] * kb1.y + qv[6] * kb1.z + qv[7] * kb1.w;
            pA += __shfl_xor_sync(0xffffffffu, pA, 4);
            pB += __shfl_xor_sync(0xffffffffu, pB, 4);
            pA += __shfl_xor_sync(0xffffffffu, pA, 2);
            pB += __shfl_xor_sync(0xffffffffu, pB, 2);
            pA += __shfl_xor_sync(0xffffffffu, pA, 1);
            pB += __shfl_xor_sync(0xffffffffu, pB, 1);
            pA += avA * qwe;
            pB += avB * qwe;
            float exA = expf(pA * 0.125f);
            float exB = expf(pB * 0.125f);
            acc[0] += exA * va0.x + exB * vb0.x;
            acc[1] += exA * va0.y + exB * vb0.y;
            acc[2] += exA * va0.z + exB * vb0.z;
            acc[3] += exA * va0.w + exB * vb0.w;
            acc[4] += exA * va1.x + exB * vb1.x;
            acc[5] += exA * va1.y + exB * vb1.y;
            acc[6] += exA * va1.z + exB * vb1.z;
            acc[7] += exA * va1.w + exB * vb1.w;
            den += exA + exB;
            exav += exA * avA + exB * avB;
        }
        if (j < e1) {
            int s = g_esrc[j];
            float av = g_eav[j];
            float4 k0 = *reinterpret_cast<const float4*>(&g_k[s * 256 + ch]);
            float4 k1 = *reinterpret_cast<const float4*>(&g_k[s * 256 + ch + 4]);
            float4 v0 = *reinterpret_cast<const float4*>(&g_v[s * 256 + ch]);
            float4 v1 = *reinterpret_cast<const float4*>(&g_v[s * 256 + ch + 4]);
            float p = qv[0] * k0.x + qv[1] * k0.y + qv[2] * k0.z + qv[3] * k0.w +
                      qv[4] * k1.x + qv[5] * k1.y + qv[6] * k1.z + qv[7] * k1.w;
            p += __shfl_xor_sync(0xffffffffu, p, 4);
            p += __shfl_xor_sync(0xffffffffu, p, 2);
            p += __shfl_xor_sync(0xffffffffu, p, 1);
            p += av * qwe;
            float ex = expf(p * 0.125f);
            acc[0] += ex * v0.x; acc[1] += ex * v0.y; acc[2] += ex * v0.z; acc[3] += ex * v0.w;
            acc[4] += ex * v1.x; acc[5] += ex * v1.y; acc[6] += ex * v1.z; acc[7] += ex * v1.w;
            den += ex;
            exav += ex * av;
        }

        float inv = (den > 0.f) ? (1.f / den) : 0.f;  // isolated node -> out = 0
        float ov[8];
#pragma unroll
        for (int i = 0; i < 8; i++) ov[i] = (acc[i] + exav * sWe[ch + i]) * inv;

        float4 x0 = *reinterpret_cast<const float4*>(&g_xr[n * 256 + ch]);
        float4 x1 = *reinterpret_cast<const float4*>(&g_xr[n * 256 + ch + 4]);
        float xv[8] = {x0.x, x0.y, x0.z, x0.w, x1.x, x1.y, x1.z, x1.w};
        float p = 0.f;
#pragma unroll
        for (int i = 0; i < 8; i++)
            p += ov[i] * sWb[ch + i] + xv[i] * sWb[256 + ch + i] + (ov[i] - xv[i]) * sWb[512 + ch + i];
#pragma unroll
        for (int off = 16; off; off >>= 1) p += __shfl_xor_sync(0xffffffffu, p, off);
        float beta = 1.f / (1.f + expf(-p));
        float r[8];
#pragma unroll
        for (int i = 0; i < 8; i++) {
            r[i] = beta * xv[i] + (1.f - beta) * ov[i];
            st[i] += r[i];
            st2[i] += r[i] * r[i];
        }
        *reinterpret_cast<float4*>(&g_h[n * 256 + ch]) = make_float4(r[0], r[1], r[2], r[3]);
        *reinterpret_cast<float4*>(&g_h[n * 256 + ch + 4]) = make_float4(r[4], r[5], r[6], r[7]);
    }

#pragma unroll
    for (int i = 0; i < 8; i++) {
        sS[warp * 256 + ch + i] = st[i];
        sS2[warp * 256 + ch + i] = st2[i];
    }
    __syncthreads();
    float ts = 0.f, ts2 = 0.f;
#pragma unroll
    for (int w = 0; w < 8; w++) {
        ts += sS[w * 256 + tid];
        ts2 += sS2[w * 256 + tid];
    }
    atomicAdd(&g_colstats[tid], ts);
    atomicAdd(&g_colstats[256 + tid], ts2);
}

// ------------------------- BN apply + ELU (layer 1: writes permuted tf32 copy) -------------------------
__global__ void bn_apply_l1_kernel(const float* __restrict__ gamma, const float* __restrict__ beta) {
    int i = blockIdx.x * blockDim.x + threadIdx.x;
    if (i >= NN * DD) return;
    int n = i >> 8, d = i & 255;
    float mu = g_colstats[d] * (1.f / NN);
    float var = g_colstats[256 + d] * (1.f / NN) - mu * mu;
    float y = gamma[d] * (g_h[i] - mu) * rsqrtf(var + BN_EPS) + beta[d];
    float r = y > 0.f ? y : expm1f(y);
    g_h[i] = r;
    g_ht[permA(n, d)] = f2tf32(r);
}

// ------------------------- BN apply + ELU + gate (layer 2) -------------------------
__global__ void bn_apply_gate_kernel(const float* __restrict__ gamma, const float* __restrict__ beta,
                                     const int* __restrict__ batch, const float* __restrict__ gW,
                                     const float* __restrict__ gb) {
    __shared__ float sgW[256];
    int tid = threadIdx.x;
    sgW[tid] = gW[tid];
    __syncthreads();
    int warp = tid >> 5, lane = tid & 31;
    int n = blockIdx.x * 8 + warp;
    if (n >= NN) return;
    int ch = lane * 8;
    float p = 0.f;
    float r[8];
#pragma unroll
    for (int i = 0; i < 8; i++) {
        int d = ch + i;
        float mu = g_colstats[d] * (1.f / NN);
        float var = g_colstats[256 + d] * (1.f / NN) - mu * mu;
        float y = gamma[d] * (g_h[n * 256 + d] - mu) * rsqrtf(var + BN_EPS) + beta[d];
        r[i] = y > 0.f ? y : expm1f(y);
        p += r[i] * sgW[d];
    }
    *reinterpret_cast<float4*>(&g_h[n * 256 + ch]) = make_float4(r[0], r[1], r[2], r[3]);
    *reinterpret_cast<float4*>(&g_h[n * 256 + ch + 4]) = make_float4(r[4], r[5], r[6], r[7]);
#pragma unroll
    for (int off = 16; off; off >>= 1) p += __shfl_xor_sync(0xffffffffu, p, off);
    if (lane == 0) {
        float ex = expf(p + gb[0]);
        g_gate[n] = ex;
        atomicAdd(&g_gden[batch[n]], ex);
    }
}

// ------------------------- readout: segment-aware pooling -------------------------
__global__ __launch_bounds__(256) void pool_seg_kernel(const int* __restrict__ batch) {
    __shared__ float sw[256];
    __shared__ int sbt[256];
    int tid = threadIdx.x;
    int n0 = blockIdx.x * 256;
    {
        int n = n0 + tid;
        int g = batch[n];
        sbt[tid] = g;
        sw[tid] = g_gate[n] / g_gden[g];
    }
    __syncthreads();
    float acc = 0.f;
    int curg = sbt[0];
    for (int i = 0; i < 256; i++) {
        int g = sbt[i];
        if (g != curg) {
            atomicAdd(&g_hG[curg * 256 + tid], acc);
            acc = 0.f;
            curg = g;
        }
        acc += sw[i] * g_h[(n0 + i) * 256 + tid];
    }
    atomicAdd(&g_hG[curg * 256 + tid], acc);
}

__global__ void final_kernel(const float* __restrict__ dW, const float* __restrict__ db,
                             const float* __restrict__ ob, float* __restrict__ out) {
    __shared__ float red[256];
    int g = blockIdx.x, t = threadIdx.x;
    red[t] = g_hG[g * 256 + t] * dW[t];
    __syncthreads();
    for (int s = 128; s > 0; s >>= 1) {
        if (t < s) red[t] += red[t + s];
        __syncthreads();
    }
    if (t == 0) out[g] = red[0] + db[0] + ob[0];
}

// ------------------------- launcher -------------------------
extern "C" void kernel_launch(void* const* d_in, const int* in_sizes, int n_in,
                              void* d_out, int out_size) {
    const float* x     = (const float*)d_in[0];
    const int*   ei    = (const int*)d_in[1];
    const float* ea    = (const float*)d_in[2];
    const int*   batch = (const int*)d_in[3];
    const float* encW  = (const float*)d_in[4];
    const float* encb  = (const float*)d_in[5];
    const float* Wq    = (const float*)d_in[6];
    const float* bq    = (const float*)d_in[7];
    const float* Wk    = (const float*)d_in[8];
    const float* bk    = (const float*)d_in[9];
    const float* Wv    = (const float*)d_in[10];
    const float* bv    = (const float*)d_in[11];
    const float* We    = (const float*)d_in[12];
    const float* Wskip = (const float*)d_in[13];
    const float* bskip = (const float*)d_in[14];
    const float* Wbeta = (const float*)d_in[15];
    const float* bng   = (const float*)d_in[16];
    const float* bnb   = (const float*)d_in[17];
    const float* gW    = (const float*)d_in[18];
    const float* gb    = (const float*)d_in[19];
    const float* dW    = (const float*)d_in[20];
    const float* db    = (const float*)d_in[21];
    const float* ob    = (const float*)d_in[22];
    float* out = (float*)d_out;

    const int* src = ei;
    const int* dst = ei + EE;

    const int TPB = 256;
    const int ND_BLOCKS = (NN * DD) / TPB;

    prep_w_kernel<<<dim3(DD * DD / TPB, 8), TPB>>>(Wq, Wk, Wv, Wskip);
    zero_readout_kernel<<<32, TPB>>>();
    zero_cnt_kernel<<<NN / TPB, TPB>>>();
    deg_hist_kernel<<<EE / TPB, TPB>>>(dst);
    scan_kernel<<<1, 1024>>>();
    zero_cnt_kernel<<<NN / TPB, TPB>>>();
    scatter_kernel<<<EE / TPB, TPB>>>(src, dst, ea);
    encoder_kernel<<<ND_BLOCKS, TPB>>>(x, encW, encb);

    for (int l = 0; l < 2; l++) {
        mma_gemm4<<<dim3(8, 256), TPB>>>(bq, bk, bv, bskip, l);
        zero_stats_kernel<<<2, TPB>>>();
        attn_combine_kernel<<<512, TPB>>>(We + l * DD, Wbeta + l * 3 * DD);
        if (l == 0) {
            bn_apply_l1_kernel<<<ND_BLOCKS, TPB>>>(bng, bnb);
        } else {
            bn_apply_gate_kernel<<<NN / 8, TPB>>>(bng + DD, bnb + DD, batch, gW, gb);
        }
    }

    pool_seg_kernel<<<NN / 256, TPB>>>(batch);
    final_kernel<<<GG, TPB>>>(dW, db, ob, out);
}

// round 14
// speedup vs baseline: 1.8984x; 1.0910x over previous
#include <cuda_runtime.h>
#include <math.h>
#include <stdint.h>

#define NN 32768
#define EE 262144
#define DD 256
#define HH 4
#define GG 32
#define BN_EPS 1e-5f

// ------------------------- scratch (device globals) -------------------------
__device__ float g_h[NN * DD];
__device__ uint32_t g_ht[NN * DD];     // tf32 copy of g_h, PERMUTED to A-fragment order
__device__ uint32_t g_wt[8 * DD * DD]; // tf32 weights, PERMUTED to B-fragment order
__device__ float g_q[NN * DD];
__device__ float g_k[NN * DD];
__device__ float g_v[NN * DD];
__device__ float g_xr[NN * DD];
__device__ float g_colstats[2 * DD];
__device__ float g_gate[NN];
__device__ float g_gden[GG];
__device__ float g_hG[GG * DD];
// CSR by dst. NOTE: scatter consumes rowptr in place; post-scatter rowptr[d] = orig_start[d+1].
__device__ int g_rowptr[NN + 1];
__device__ int g_cnt[NN];
__device__ int g_esrc[EE];
__device__ float g_eav[EE];

__device__ __forceinline__ uint32_t f2tf32(float f) {
    uint32_t r;
    asm("cvt.rna.tf32.f32 %0, %1;" : "=r"(r) : "f"(f));
    return r;
}

// A-fragment permutation: for 16-row x 8-col blocks, thread quad {(g,t),(g+8,t),(g,t+4),(g+8,t+4)}
// stored contiguously. index = ((rg*32 + kb)*32 + lane)*4 + elem.
__device__ __forceinline__ int permA(int n, int d) {
    int rg = n >> 4, kb = d >> 3;
    int lane = (n & 7) * 4 + (d & 3);
    int elem = ((n >> 3) & 1) + ((d >> 2) & 1) * 2;
    return ((rg * 32 + kb) * 32 + lane) * 4 + elem;
}

// ------------------------- small zero kernels -------------------------
__global__ void zero_cnt_kernel() {
    int i = blockIdx.x * blockDim.x + threadIdx.x;
    if (i < NN) g_cnt[i] = 0;
}
__global__ void zero_stats_kernel() {
    int i = blockIdx.x * blockDim.x + threadIdx.x;
    if (i < 2 * DD) g_colstats[i] = 0.f;
}
__global__ void zero_readout_kernel() {
    int i = blockIdx.x * blockDim.x + threadIdx.x;
    if (i < GG * DD) g_hG[i] = 0.f;
    if (i < GG) g_gden[i] = 0.f;
}

// ------------------------- CSR build -------------------------
__global__ void deg_hist_kernel(const int* __restrict__ dst) {
    int e = blockIdx.x * blockDim.x + threadIdx.x;
    if (e < EE) atomicAdd(&g_cnt[dst[e]], 1);
}

__global__ void scan_kernel() {
    __shared__ int swarp[32];
    __shared__ int carry;
    int tid = threadIdx.x;
    int lane = tid & 31, w = tid >> 5;
    if (tid == 0) carry = 0;
    __syncthreads();
    for (int base = 0; base < NN; base += 1024) {
        int x = g_cnt[base + tid];
#pragma unroll
        for (int o = 1; o < 32; o <<= 1) {
            int y = __shfl_up_sync(0xffffffffu, x, o);
            if (lane >= o) x += y;
        }
        if (lane == 31) swarp[w] = x;
        __syncthreads();
        if (w == 0) {
            int y = swarp[lane];
#pragma unroll
            for (int o = 1; o < 32; o <<= 1) {
                int z = __shfl_up_sync(0xffffffffu, y, o);
                if (lane >= o) y += z;
            }
            swarp[lane] = y;
        }
        __syncthreads();
        int incl = x + (w > 0 ? swarp[w - 1] : 0) + carry;
        g_rowptr[base + tid + 1] = incl;
        __syncthreads();
        if (tid == 1023) carry = incl;
        __syncthreads();
    }
    if (tid == 0) g_rowptr[0] = 0;
}

// Consumes g_rowptr in place: pos = old value; post-scatter g_rowptr[d] = orig_start[d+1].
// scan_kernel rebuilds rowptr each launch, so this is replay-idempotent.
__global__ void scatter_kernel(const int* __restrict__ src, const int* __restrict__ dst,
                               const float* __restrict__ ea) {
    int e = blockIdx.x * blockDim.x + threadIdx.x;
    if (e >= EE) return;
    int d = dst[e];
    int pos = atomicAdd(&g_rowptr[d], 1);
    g_esrc[pos] = src[e];
    g_eav[pos] = ea[e];
}

// ------------------------- weight prep: tf32 + B-fragment permutation -------------------------
__global__ void prep_w_kernel(const float* __restrict__ Wq, const float* __restrict__ Wk,
                              const float* __restrict__ Wv, const float* __restrict__ Ws) {
    int m = blockIdx.y;            // 0..7 : layer*4 + which
    int i = blockIdx.x * blockDim.x + threadIdx.x;   // 0..65535
    int l = m >> 2, w = m & 3;
    const float* S = ((w == 0) ? Wq : (w == 1) ? Wk : (w == 2) ? Wv : Ws) + (size_t)l * DD * DD;
    int kb = i >> 11;
    int rem = i & 2047;
    int nb = rem >> 8;
    int o = rem & 255;
    int pairidx = (o >> 7) & 1;
    int lq = (o >> 2) & 31;
    int e = o & 3;
    int fn = pairidx * 2 + (e >> 1);
    int half = e & 1;
    int gid = lq >> 2, tig = lq & 3;
    int k = kb * 8 + tig + half * 4;
    int n = nb * 32 + fn * 8 + gid;
    g_wt[(size_t)m * 65536 + i] = f2tf32(S[k * 256 + n]);
}

// ------------------------- encoder (writes permuted tf32 copy) -------------------------
__global__ void encoder_kernel(const float* __restrict__ x,
                               const float* __restrict__ W,
                               const float* __restrict__ b) {
    int i = blockIdx.x * blockDim.x + threadIdx.x;
    if (i >= NN * DD) return;
    int n = i >> 8, d = i & 255;
    float h = x[n * 2] * W[d] + x[n * 2 + 1] * W[DD + d] + b[d];
    g_h[i] = h;
    g_ht[permA(n, d)] = f2tf32(h);
}

// ------------------------- TF32 mma.sync GEMM, 3-stage pipeline, LDS.128 fragments ----------
__device__ __forceinline__ void cp16(uint32_t s, const void* g) {
    asm volatile("cp.async.ca.shared.global [%0], [%1], 16;" :: "r"(s), "l"(g));
}

__device__ __forceinline__ void mma8(float* c, const uint32_t* a, const uint32_t* b) {
    asm volatile(
        "mma.sync.aligned.m16n8k8.row.col.f32.tf32.tf32.f32 "
        "{%0,%1,%2,%3}, {%4,%5,%6,%7}, {%8,%9}, {%0,%1,%2,%3};"
        : "+f"(c[0]), "+f"(c[1]), "+f"(c[2]), "+f"(c[3])
        : "r"(a[0]), "r"(a[1]), "r"(a[2]), "r"(a[3]), "r"(b[0]), "r"(b[1]));
}

__global__ __launch_bounds__(256, 2) void mma_gemm4(const float* __restrict__ bq,
                                                    const float* __restrict__ bk,
                                                    const float* __restrict__ bv,
                                                    const float* __restrict__ bs,
                                                    int layer) {
    __shared__ uint32_t As[3][2048];  // [rg 8][kb 2][128]
    __shared__ uint32_t Bs[3][2048];  // [kb 2][nb 4][256]

    int mat = blockIdx.x >> 1;
    int bn = (blockIdx.x & 1) * 128;
    int bm = blockIdx.y * 128;
    const float* bias = ((mat == 0) ? bq : (mat == 1) ? bk : (mat == 2) ? bv : bs) + layer * DD;
    float* Cm = (mat == 0) ? g_q : (mat == 1) ? g_k : (mat == 2) ? g_v : g_xr;
    const uint32_t* A = g_ht;
    const uint32_t* B = g_wt + (size_t)(layer * 4 + mat) * 65536;

    int tid = threadIdx.x;
    int warp = tid >> 5, lane = tid & 31;
    int gid = lane >> 2, tig = lane & 3;
    int warp_m = (warp & 1) * 64;
    int warp_n = (warp >> 1) * 32;
    int rg_w = (warp & 1) * 4;
    int nb_w = warp >> 1;
    int rgbase = bm >> 4;
    int nbbase = bn >> 5;

    float acc[4][4][4];
#pragma unroll
    for (int i = 0; i < 4; i++)
#pragma unroll
        for (int j = 0; j < 4; j++)
#pragma unroll
            for (int r = 0; r < 4; r++) acc[i][j][r] = 0.f;

    uint32_t as_base = (uint32_t)__cvta_generic_to_shared(&As[0][0]);
    uint32_t bs_base = (uint32_t)__cvta_generic_to_shared(&Bs[0][0]);

    auto load_tiles = [&](int buf, int k0) {
        int kb0 = k0 >> 3;
#pragma unroll
        for (int i = 0; i < 2; i++) {
            int slot = tid + i * 256;                 // 0..511
            int rg_i = slot >> 6, kb_i = (slot >> 5) & 1, ch = slot & 31;
            cp16(as_base + (uint32_t)(buf * 2048 + (rg_i * 2 + kb_i) * 128 + ch * 4) * 4u,
                 &A[(size_t)((rgbase + rg_i) * 32 + kb0 + kb_i) * 128 + ch * 4]);
            int kb_j = slot >> 8, nb_j = (slot >> 6) & 3, ch2 = slot & 63;
            cp16(bs_base + (uint32_t)(buf * 2048 + (kb_j * 4 + nb_j) * 256 + ch2 * 4) * 4u,
                 &B[(size_t)((kb0 + kb_j) * 8 + nbbase + nb_j) * 256 + ch2 * 4]);
        }
    };

    // 3-stage pipeline: prologue fills buffers 0,1
    load_tiles(0, 0);
    asm volatile("cp.async.commit_group;");
    load_tiles(1, 16);
    asm volatile("cp.async.commit_group;");

    for (int it = 0; it < 16; it++) {
        asm volatile("cp.async.wait_group 1;");
        __syncthreads();
        // prefetch it+2 into buffer (it+2)%3 (last computed at it-1; sync above protects it)
        if (it + 2 < 16) load_tiles((it + 2) % 3, (it + 2) * 16);
        asm volatile("cp.async.commit_group;");   // empty group at tail keeps wait counts valid

        int buf = it % 3;
#pragma unroll
        for (int ksb = 0; ksb < 2; ksb++) {
            const uint4* bp = reinterpret_cast<const uint4*>(
                &Bs[buf][(ksb * 4 + nb_w) * 256 + lane * 4]);
            uint4 b01 = bp[0];
            uint4 b23 = bp[32];
            uint32_t bfr[4][2] = {{b01.x, b01.y}, {b01.z, b01.w},
                                  {b23.x, b23.y}, {b23.z, b23.w}};
#pragma unroll
            for (int fm = 0; fm < 4; fm++) {
                uint4 a = *reinterpret_cast<const uint4*>(
                    &As[buf][((rg_w + fm) * 2 + ksb) * 128 + lane * 4]);
                uint32_t afr[4] = {a.x, a.y, a.z, a.w};
#pragma unroll
                for (int fn = 0; fn < 4; fn++) mma8(acc[fm][fn], afr, bfr[fn]);
            }
        }
    }

#pragma unroll
    for (int fm = 0; fm < 4; fm++) {
        int row = bm + warp_m + fm * 16 + gid;
#pragma unroll
        for (int fn = 0; fn < 4; fn++) {
            int col = bn + warp_n + fn * 8 + tig * 2;
            float b0 = bias[col], b1 = bias[col + 1];
            float2 o0 = make_float2(acc[fm][fn][0] + b0, acc[fm][fn][1] + b1);
            float2 o1 = make_float2(acc[fm][fn][2] + b0, acc[fm][fn][3] + b1);
            *reinterpret_cast<float2*>(&Cm[(size_t)row * 256 + col]) = o0;
            *reinterpret_cast<float2*>(&Cm[(size_t)(row + 8) * 256 + col]) = o1;
        }
    }
}

// ------------------------- fused attention + combine + BN-stats (4-edge unrolled gather) ----------
// Uses shifted rowptr: e0 = rowptr[n-1] (0 for n==0), e1 = rowptr[n].
__global__ __launch_bounds__(256) void attn_combine_kernel(const float* __restrict__ We,
                                                           const float* __restrict__ Wb) {
    __shared__ float sWe[256];
    __shared__ float sWb[768];
    __shared__ float sS[8 * 256];
    __shared__ float sS2[8 * 256];
    int tid = threadIdx.x;
    sWe[tid] = We[tid];
    sWb[tid] = Wb[tid];
    sWb[tid + 256] = Wb[tid + 256];
    sWb[tid + 512] = Wb[tid + 512];
    __syncthreads();
    int warp = tid >> 5, lane = tid & 31;
    int head = lane >> 3;
    int ch = head * 64 + (lane & 7) * 8;

    float st[8], st2[8];
#pragma unroll
    for (int i = 0; i < 8; i++) { st[i] = 0.f; st2[i] = 0.f; }

    for (int it = 0; it < 8; it++) {
        int n = blockIdx.x * 64 + it * 8 + warp;

        float4 q0 = *reinterpret_cast<const float4*>(&g_q[n * 256 + ch]);
        float4 q1 = *reinterpret_cast<const float4*>(&g_q[n * 256 + ch + 4]);
        float qv[8] = {q0.x, q0.y, q0.z, q0.w, q1.x, q1.y, q1.z, q1.w};
        float qwe = 0.f;
#pragma unroll
        for (int i = 0; i < 8; i++) qwe += qv[i] * sWe[ch + i];
        qwe += __shfl_xor_sync(0xffffffffu, qwe, 4);
        qwe += __shfl_xor_sync(0xffffffffu, qwe, 2);
        qwe += __shfl_xor_sync(0xffffffffu, qwe, 1);

        int e0 = (n == 0) ? 0 : g_rowptr[n - 1];
        int e1 = g_rowptr[n];
        float acc[8];
#pragma unroll
        for (int i = 0; i < 8; i++) acc[i] = 0.f;
        float den = 0.f, exav = 0.f;

        int j = e0;
        // unroll by 4: four independent load/dot/shfl/exp chains in flight
        for (; j + 3 < e1; j += 4) {
            int ss[4];
            float avv[4], pp[4], ee[4];
            float4 kk0[4], kk1[4], vv0[4], vv1[4];
#pragma unroll
            for (int u = 0; u < 4; u++) {
                ss[u] = g_esrc[j + u];
                avv[u] = g_eav[j + u];
            }
#pragma unroll
            for (int u = 0; u < 4; u++) {
                kk0[u] = *reinterpret_cast<const float4*>(&g_k[ss[u] * 256 + ch]);
                kk1[u] = *reinterpret_cast<const float4*>(&g_k[ss[u] * 256 + ch + 4]);
                vv0[u] = *reinterpret_cast<const float4*>(&g_v[ss[u] * 256 + ch]);
                vv1[u] = *reinterpret_cast<const float4*>(&g_v[ss[u] * 256 + ch + 4]);
            }
#pragma unroll
            for (int u = 0; u < 4; u++)
                pp[u] = qv[0] * kk0[u].x + qv[1] * kk0[u].y + qv[2] * kk0[u].z + qv[3] * kk0[u].w +
                        qv[4] * kk1[u].x + qv[5] * kk1[u].y + qv[6] * kk1[u].z + qv[7] * kk1[u].w;
#pragma unroll
            for (int u = 0; u < 4; u++) pp[u] += __shfl_xor_sync(0xffffffffu, pp[u], 4);
#pragma unroll
            for (int u = 0; u < 4; u++) pp[u] += __shfl_xor_sync(0xffffffffu, pp[u], 2);
#pragma unroll
            for (int u = 0; u < 4; u++) pp[u] += __shfl_xor_sync(0xffffffffu, pp[u], 1);
#pragma unroll
            for (int u = 0; u < 4; u++) ee[u] = expf((pp[u] + avv[u] * qwe) * 0.125f);
#pragma unroll
            for (int u = 0; u < 4; u++) {
                acc[0] += ee[u] * vv0[u].x;
                acc[1] += ee[u] * vv0[u].y;
                acc[2] += ee[u] * vv0[u].z;
                acc[3] += ee[u] * vv0[u].w;
                acc[4] += ee[u] * vv1[u].x;
                acc[5] += ee[u] * vv1[u].y;
                acc[6] += ee[u] * vv1[u].z;
                acc[7] += ee[u] * vv1[u].w;
                den += ee[u];
                exav += ee[u] * avv[u];
            }
        }
        for (; j < e1; j++) {
            int s = g_esrc[j];
            float av = g_eav[j];
            float4 k0 = *reinterpret_cast<const float4*>(&g_k[s * 256 + ch]);
            float4 k1 = *reinterpret_cast<const float4*>(&g_k[s * 256 + ch + 4]);
            float4 v0 = *reinterpret_cast<const float4*>(&g_v[s * 256 + ch]);
            float4 v1 = *reinterpret_cast<const float4*>(&g_v[s * 256 + ch + 4]);
            float p = qv[0] * k0.x + qv[1] * k0.y + qv[2] * k0.z + qv[3] * k0.w +
                      qv[4] * k1.x + qv[5] * k1.y + qv[6] * k1.z + qv[7] * k1.w;
            p += __shfl_xor_sync(0xffffffffu, p, 4);
            p += __shfl_xor_sync(0xffffffffu, p, 2);
            p += __shfl_xor_sync(0xffffffffu, p, 1);
            p += av * qwe;
            float ex = expf(p * 0.125f);  // scale=1/sqrt(64); max-shift cancels in ratio
            acc[0] += ex * v0.x; acc[1] += ex * v0.y; acc[2] += ex * v0.z; acc[3] += ex * v0.w;
            acc[4] += ex * v1.x; acc[5] += ex * v1.y; acc[6] += ex * v1.z; acc[7] += ex * v1.w;
            den += ex;
            exav += ex * av;
        }

        float inv = (den > 0.f) ? (1.f / den) : 0.f;  // isolated node -> out = 0
        float ov[8];
#pragma unroll
        for (int i = 0; i < 8; i++) ov[i] = (acc[i] + exav * sWe[ch + i]) * inv;

        float4 x0 = *reinterpret_cast<const float4*>(&g_xr[n * 256 + ch]);
        float4 x1 = *reinterpret_cast<const float4*>(&g_xr[n * 256 + ch + 4]);
        float xv[8] = {x0.x, x0.y, x0.z, x0.w, x1.x, x1.y, x1.z, x1.w};
        float p = 0.f;
#pragma unroll
        for (int i = 0; i < 8; i++)
            p += ov[i] * sWb[ch + i] + xv[i] * sWb[256 + ch + i] + (ov[i] - xv[i]) * sWb[512 + ch + i];
#pragma unroll
        for (int off = 16; off; off >>= 1) p += __shfl_xor_sync(0xffffffffu, p, off);
        float beta = 1.f / (1.f + expf(-p));
        float r[8];
#pragma unroll
        for (int i = 0; i < 8; i++) {
            r[i] = beta * xv[i] + (1.f - beta) * ov[i];
            st[i] += r[i];
            st2[i] += r[i] * r[i];
        }
        *reinterpret_cast<float4*>(&g_h[n * 256 + ch]) = make_float4(r[0], r[1], r[2], r[3]);
        *reinterpret_cast<float4*>(&g_h[n * 256 + ch + 4]) = make_float4(r[4], r[5], r[6], r[7]);
    }

#pragma unroll
    for (int i = 0; i < 8; i++) {
        sS[warp * 256 + ch + i] = st[i];
        sS2[warp * 256 + ch + i] = st2[i];
    }
    __syncthreads();
    float ts = 0.f, ts2 = 0.f;
#pragma unroll
    for (int w = 0; w < 8; w++) {
        ts += sS[w * 256 + tid];
        ts2 += sS2[w * 256 + tid];
    }
    atomicAdd(&g_colstats[tid], ts);
    atomicAdd(&g_colstats[256 + tid], ts2);
}

// ------------------------- BN apply + ELU (layer 1: writes permuted tf32 copy) -------------------------
__global__ void bn_apply_l1_kernel(const float* __restrict__ gamma, const float* __restrict__ beta) {
    int i = blockIdx.x * blockDim.x + threadIdx.x;
    if (i >= NN * DD) return;
    int n = i >> 8, d = i & 255;
    float mu = g_colstats[d] * (1.f / NN);
    float var = g_colstats[256 + d] * (1.f / NN) - mu * mu;
    float y = gamma[d] * (g_h[i] - mu) * rsqrtf(var + BN_EPS) + beta[d];
    float r = y > 0.f ? y : expm1f(y);
    g_h[i] = r;
    g_ht[permA(n, d)] = f2tf32(r);
}

// ------------------------- BN apply + ELU + gate (layer 2) -------------------------
__global__ void bn_apply_gate_kernel(const float* __restrict__ gamma, const float* __restrict__ beta,
                                     const int* __restrict__ batch, const float* __restrict__ gW,
                                     const float* __restrict__ gb) {
    __shared__ float sgW[256];
    int tid = threadIdx.x;
    sgW[tid] = gW[tid];
    __syncthreads();
    int warp = tid >> 5, lane = tid & 31;
    int n = blockIdx.x * 8 + warp;
    if (n >= NN) return;
    int ch = lane * 8;
    float p = 0.f;
    float r[8];
#pragma unroll
    for (int i = 0; i < 8; i++) {
        int d = ch + i;
        float mu = g_colstats[d] * (1.f / NN);
        float var = g_colstats[256 + d] * (1.f / NN) - mu * mu;
        float y = gamma[d] * (g_h[n * 256 + d] - mu) * rsqrtf(var + BN_EPS) + beta[d];
        r[i] = y > 0.f ? y : expm1f(y);
        p += r[i] * sgW[d];
    }
    *reinterpret_cast<float4*>(&g_h[n * 256 + ch]) = make_float4(r[0], r[1], r[2], r[3]);
    *reinterpret_cast<float4*>(&g_h[n * 256 + ch + 4]) = make_float4(r[4], r[5], r[6], r[7]);
#pragma unroll
    for (int off = 16; off; off >>= 1) p += __shfl_xor_sync(0xffffffffu, p, off);
    if (lane == 0) {
        float ex = expf(p + gb[0]);
        g_gate[n] = ex;
        atomicAdd(&g_gden[batch[n]], ex);
    }
}

// ------------------------- readout: segment-aware pooling -------------------------
__global__ __launch_bounds__(256) void pool_seg_kernel(const int* __restrict__ batch) {
    __shared__ float sw[256];
    __shared__ int sbt[256];
    int tid = threadIdx.x;
    int n0 = blockIdx.x * 256;
    {
        int n = n0 + tid;
        int g = batch[n];
        sbt[tid] = g;
        sw[tid] = g_gate[n] / g_gden[g];
    }
    __syncthreads();
    float acc = 0.f;
    int curg = sbt[0];
    for (int i = 0; i < 256; i++) {
        int g = sbt[i];
        if (g != curg) {
            atomicAdd(&g_hG[curg * 256 + tid], acc);
            acc = 0.f;
            curg = g;
        }
        acc += sw[i] * g_h[(n0 + i) * 256 + tid];
    }
    atomicAdd(&g_hG[curg * 256 + tid], acc);
}

__global__ void final_kernel(const float* __restrict__ dW, const float* __restrict__ db,
                             const float* __restrict__ ob, float* __restrict__ out) {
    __shared__ float red[256];
    int g = blockIdx.x, t = threadIdx.x;
    red[t] = g_hG[g * 256 + t] * dW[t];
    __syncthreads();
    for (int s = 128; s > 0; s >>= 1) {
        if (t < s) red[t] += red[t + s];
        __syncthreads();
    }
    if (t == 0) out[g] = red[0] + db[0] + ob[0];
}

// ------------------------- launcher -------------------------
extern "C" void kernel_launch(void* const* d_in, const int* in_sizes, int n_in,
                              void* d_out, int out_size) {
    const float* x     = (const float*)d_in[0];
    const int*   ei    = (const int*)d_in[1];
    const float* ea    = (const float*)d_in[2];
    const int*   batch = (const int*)d_in[3];
    const float* encW  = (const float*)d_in[4];
    const float* encb  = (const float*)d_in[5];
    const float* Wq    = (const float*)d_in[6];
    const float* bq    = (const float*)d_in[7];
    const float* Wk    = (const float*)d_in[8];
    const float* bk    = (const float*)d_in[9];
    const float* Wv    = (const float*)d_in[10];
    const float* bv    = (const float*)d_in[11];
    const float* We    = (const float*)d_in[12];
    const float* Wskip = (const float*)d_in[13];
    const float* bskip = (const float*)d_in[14];
    const float* Wbeta = (const float*)d_in[15];
    const float* bng   = (const float*)d_in[16];
    const float* bnb   = (const float*)d_in[17];
    const float* gW    = (const float*)d_in[18];
    const float* gb    = (const float*)d_in[19];
    const float* dW    = (const float*)d_in[20];
    const float* db    = (const float*)d_in[21];
    const float* ob    = (const float*)d_in[22];
    float* out = (float*)d_out;

    const int* src = ei;
    const int* dst = ei + EE;

    const int TPB = 256;
    const int ND_BLOCKS = (NN * DD) / TPB;

    prep_w_kernel<<<dim3(DD * DD / TPB, 8), TPB>>>(Wq, Wk, Wv, Wskip);
    zero_readout_kernel<<<32, TPB>>>();
    zero_cnt_kernel<<<NN / TPB, TPB>>>();
    deg_hist_kernel<<<EE / TPB, TPB>>>(dst);
    scan_kernel<<<1, 1024>>>();
    scatter_kernel<<<EE / TPB, TPB>>>(src, dst, ea);
    encoder_kernel<<<ND_BLOCKS, TPB>>>(x, encW, encb);

    for (int l = 0; l < 2; l++) {
        mma_gemm4<<<dim3(8, 256), TPB>>>(bq, bk, bv, bskip, l);
        zero_stats_kernel<<<2, TPB>>>();
        attn_combine_kernel<<<512, TPB>>>(We + l * DD, Wbeta + l * 3 * DD);
        if (l == 0) {
            bn_apply_l1_kernel<<<ND_BLOCKS, TPB>>>(bng, bnb);
        } else {
            bn_apply_gate_kernel<<<NN / 8, TPB>>>(bng + DD, bnb + DD, batch, gW, gb);
        }
    }

    pool_seg_kernel<<<NN / 256, TPB>>>(batch);
    final_kernel<<<GG, TPB>>>(dW, db, ob, out);
}

// round 15
// speedup vs baseline: 2.0003x; 1.0537x over previous
#include <cuda_runtime.h>
#include <math.h>
#include <stdint.h>

#define NN 32768
#define EE 262144
#define DD 256
#define HH 4
#define GG 32
#define BN_EPS 1e-5f

// ------------------------- scratch (device globals) -------------------------
__device__ float g_h[NN * DD];
__device__ uint32_t g_ht[NN * DD];     // tf32 copy of g_h, PERMUTED to A-fragment order
__device__ uint32_t g_wt[8 * DD * DD]; // tf32 weights, PERMUTED to B-fragment order
__device__ float g_q[NN * DD];
__device__ float g_k[NN * DD];
__device__ float g_v[NN * DD];
__device__ float g_xr[NN * DD];
__device__ float g_colstats[2 * DD];
__device__ float g_gate[NN];
__device__ float g_gden[GG];
__device__ float g_hG[GG * DD];
// CSR by dst. scatter consumes rowptr in place; post-scatter rowptr[d] = orig_start[d+1].
__device__ int g_rowptr[NN + 1];
__device__ int g_cnt[NN];
__device__ int g_esrc[EE];
__device__ float g_eav[EE];

__device__ __forceinline__ uint32_t f2tf32(float f) {
    uint32_t r;
    asm("cvt.rna.tf32.f32 %0, %1;" : "=r"(r) : "f"(f));
    return r;
}

// A-fragment permutation: index = ((rg*32 + kb)*32 + lane)*4 + elem.
__device__ __forceinline__ int permA(int n, int d) {
    int rg = n >> 4, kb = d >> 3;
    int lane = (n & 7) * 4 + (d & 3);
    int elem = ((n >> 3) & 1) + ((d >> 2) & 1) * 2;
    return ((rg * 32 + kb) * 32 + lane) * 4 + elem;
}

// ------------------------- merged zero kernel (cnt + readout) -------------------------
__global__ void zero_prep_kernel() {
    int i = blockIdx.x * blockDim.x + threadIdx.x;
    if (i < NN) g_cnt[i] = 0;
    if (i < GG * DD) g_hG[i] = 0.f;
    if (i < GG) g_gden[i] = 0.f;
}

// ------------------------- CSR build -------------------------
__global__ void deg_hist_kernel(const int* __restrict__ dst) {
    int e = blockIdx.x * blockDim.x + threadIdx.x;
    if (e < EE) atomicAdd(&g_cnt[dst[e]], 1);
}

__global__ void scan_kernel() {
    __shared__ int swarp[32];
    __shared__ int carry;
    int tid = threadIdx.x;
    int lane = tid & 31, w = tid >> 5;
    if (tid == 0) carry = 0;
    __syncthreads();
    for (int base = 0; base < NN; base += 1024) {
        int x = g_cnt[base + tid];
#pragma unroll
        for (int o = 1; o < 32; o <<= 1) {
            int y = __shfl_up_sync(0xffffffffu, x, o);
            if (lane >= o) x += y;
        }
        if (lane == 31) swarp[w] = x;
        __syncthreads();
        if (w == 0) {
            int y = swarp[lane];
#pragma unroll
            for (int o = 1; o < 32; o <<= 1) {
                int z = __shfl_up_sync(0xffffffffu, y, o);
                if (lane >= o) y += z;
            }
            swarp[lane] = y;
        }
        __syncthreads();
        int incl = x + (w > 0 ? swarp[w - 1] : 0) + carry;
        g_rowptr[base + tid + 1] = incl;
        __syncthreads();
        if (tid == 1023) carry = incl;
        __syncthreads();
    }
    if (tid == 0) g_rowptr[0] = 0;
}

// Consumes g_rowptr in place; scan_kernel rebuilds it each launch (replay-idempotent).
__global__ void scatter_kernel(const int* __restrict__ src, const int* __restrict__ dst,
                               const float* __restrict__ ea) {
    int e = blockIdx.x * blockDim.x + threadIdx.x;
    if (e >= EE) return;
    int d = dst[e];
    int pos = atomicAdd(&g_rowptr[d], 1);
    g_esrc[pos] = src[e];
    g_eav[pos] = ea[e];
}

// ------------------------- weight prep: tf32 + B-fragment permutation -------------------------
__global__ void prep_w_kernel(const float* __restrict__ Wq, const float* __restrict__ Wk,
                              const float* __restrict__ Wv, const float* __restrict__ Ws) {
    int m = blockIdx.y;            // 0..7 : layer*4 + which
    int i = blockIdx.x * blockDim.x + threadIdx.x;   // 0..65535
    int l = m >> 2, w = m & 3;
    const float* S = ((w == 0) ? Wq : (w == 1) ? Wk : (w == 2) ? Wv : Ws) + (size_t)l * DD * DD;
    int kb = i >> 11;
    int rem = i & 2047;
    int nb = rem >> 8;
    int o = rem & 255;
    int pairidx = (o >> 7) & 1;
    int lq = (o >> 2) & 31;
    int e = o & 3;
    int fn = pairidx * 2 + (e >> 1);
    int half = e & 1;
    int gid = lq >> 2, tig = lq & 3;
    int k = kb * 8 + tig + half * 4;
    int n = nb * 32 + fn * 8 + gid;
    g_wt[(size_t)m * 65536 + i] = f2tf32(S[k * 256 + n]);
}

// ------------------------- encoder (float4-vectorized; writes permuted tf32 copy) ----------
__global__ void encoder_kernel(const float* __restrict__ x,
                               const float* __restrict__ W,
                               const float* __restrict__ b) {
    int i = blockIdx.x * blockDim.x + threadIdx.x;   // over NN*64 float4s
    if (i >= NN * 64) return;
    int n = i >> 6, d4 = (i & 63) * 4;
    float x0 = x[n * 2], x1 = x[n * 2 + 1];
    float4 w0 = *reinterpret_cast<const float4*>(&W[d4]);
    float4 w1 = *reinterpret_cast<const float4*>(&W[DD + d4]);
    float4 bb = *reinterpret_cast<const float4*>(&b[d4]);
    float4 h;
    h.x = x0 * w0.x + x1 * w1.x + bb.x;
    h.y = x0 * w0.y + x1 * w1.y + bb.y;
    h.z = x0 * w0.z + x1 * w1.z + bb.z;
    h.w = x0 * w0.w + x1 * w1.w + bb.w;
    *reinterpret_cast<float4*>(&g_h[n * 256 + d4]) = h;
    g_ht[permA(n, d4 + 0)] = f2tf32(h.x);
    g_ht[permA(n, d4 + 1)] = f2tf32(h.y);
    g_ht[permA(n, d4 + 2)] = f2tf32(h.z);
    g_ht[permA(n, d4 + 3)] = f2tf32(h.w);
}

// ------------------------- TF32 mma.sync GEMM, 3-stage pipeline, LDS.128 fragments ----------
__device__ __forceinline__ void cp16(uint32_t s, const void* g) {
    asm volatile("cp.async.ca.shared.global [%0], [%1], 16;" :: "r"(s), "l"(g));
}

__device__ __forceinline__ void mma8(float* c, const uint32_t* a, const uint32_t* b) {
    asm volatile(
        "mma.sync.aligned.m16n8k8.row.col.f32.tf32.tf32.f32 "
        "{%0,%1,%2,%3}, {%4,%5,%6,%7}, {%8,%9}, {%0,%1,%2,%3};"
        : "+f"(c[0]), "+f"(c[1]), "+f"(c[2]), "+f"(c[3])
        : "r"(a[0]), "r"(a[1]), "r"(a[2]), "r"(a[3]), "r"(b[0]), "r"(b[1]));
}

__global__ __launch_bounds__(256, 2) void mma_gemm4(const float* __restrict__ bq,
                                                    const float* __restrict__ bk,
                                                    const float* __restrict__ bv,
                                                    const float* __restrict__ bs,
                                                    int layer) {
    __shared__ uint32_t As[3][2048];
    __shared__ uint32_t Bs[3][2048];

    // fold colstats zeroing into the GEMM (runs between prior BN-read and next attn-add)
    if (blockIdx.x == 0 && blockIdx.y == 0) {
        if (threadIdx.x < 256) {
            g_colstats[threadIdx.x] = 0.f;
            g_colstats[256 + threadIdx.x] = 0.f;
        }
    }

    int mat = blockIdx.x >> 1;
    int bn = (blockIdx.x & 1) * 128;
    int bm = blockIdx.y * 128;
    const float* bias = ((mat == 0) ? bq : (mat == 1) ? bk : (mat == 2) ? bv : bs) + layer * DD;
    float* Cm = (mat == 0) ? g_q : (mat == 1) ? g_k : (mat == 2) ? g_v : g_xr;
    const uint32_t* A = g_ht;
    const uint32_t* B = g_wt + (size_t)(layer * 4 + mat) * 65536;

    int tid = threadIdx.x;
    int warp = tid >> 5, lane = tid & 31;
    int gid = lane >> 2, tig = lane & 3;
    int warp_m = (warp & 1) * 64;
    int warp_n = (warp >> 1) * 32;
    int rg_w = (warp & 1) * 4;
    int nb_w = warp >> 1;
    int rgbase = bm >> 4;
    int nbbase = bn >> 5;

    float acc[4][4][4];
#pragma unroll
    for (int i = 0; i < 4; i++)
#pragma unroll
        for (int j = 0; j < 4; j++)
#pragma unroll
            for (int r = 0; r < 4; r++) acc[i][j][r] = 0.f;

    uint32_t as_base = (uint32_t)__cvta_generic_to_shared(&As[0][0]);
    uint32_t bs_base = (uint32_t)__cvta_generic_to_shared(&Bs[0][0]);

    auto load_tiles = [&](int buf, int k0) {
        int kb0 = k0 >> 3;
#pragma unroll
        for (int i = 0; i < 2; i++) {
            int slot = tid + i * 256;
            int rg_i = slot >> 6, kb_i = (slot >> 5) & 1, ch = slot & 31;
            cp16(as_base + (uint32_t)(buf * 2048 + (rg_i * 2 + kb_i) * 128 + ch * 4) * 4u,
                 &A[(size_t)((rgbase + rg_i) * 32 + kb0 + kb_i) * 128 + ch * 4]);
            int kb_j = slot >> 8, nb_j = (slot >> 6) & 3, ch2 = slot & 63;
            cp16(bs_base + (uint32_t)(buf * 2048 + (kb_j * 4 + nb_j) * 256 + ch2 * 4) * 4u,
                 &B[(size_t)((kb0 + kb_j) * 8 + nbbase + nb_j) * 256 + ch2 * 4]);
        }
    };

    load_tiles(0, 0);
    asm volatile("cp.async.commit_group;");
    load_tiles(1, 16);
    asm volatile("cp.async.commit_group;");

    for (int it = 0; it < 16; it++) {
        asm volatile("cp.async.wait_group 1;");
        __syncthreads();
        if (it + 2 < 16) load_tiles((it + 2) % 3, (it + 2) * 16);
        asm volatile("cp.async.commit_group;");

        int buf = it % 3;
#pragma unroll
        for (int ksb = 0; ksb < 2; ksb++) {
            const uint4* bp = reinterpret_cast<const uint4*>(
                &Bs[buf][(ksb * 4 + nb_w) * 256 + lane * 4]);
            uint4 b01 = bp[0];
            uint4 b23 = bp[32];
            uint32_t bfr[4][2] = {{b01.x, b01.y}, {b01.z, b01.w},
                                  {b23.x, b23.y}, {b23.z, b23.w}};
#pragma unroll
            for (int fm = 0; fm < 4; fm++) {
                uint4 a = *reinterpret_cast<const uint4*>(
                    &As[buf][((rg_w + fm) * 2 + ksb) * 128 + lane * 4]);
                uint32_t afr[4] = {a.x, a.y, a.z, a.w};
#pragma unroll
                for (int fn = 0; fn < 4; fn++) mma8(acc[fm][fn], afr, bfr[fn]);
            }
        }
    }

#pragma unroll
    for (int fm = 0; fm < 4; fm++) {
        int row = bm + warp_m + fm * 16 + gid;
#pragma unroll
        for (int fn = 0; fn < 4; fn++) {
            int col = bn + warp_n + fn * 8 + tig * 2;
            float b0 = bias[col], b1 = bias[col + 1];
            float2 o0 = make_float2(acc[fm][fn][0] + b0, acc[fm][fn][1] + b1);
            float2 o1 = make_float2(acc[fm][fn][2] + b0, acc[fm][fn][3] + b1);
            *reinterpret_cast<float2*>(&Cm[(size_t)row * 256 + col]) = o0;
            *reinterpret_cast<float2*>(&Cm[(size_t)(row + 8) * 256 + col]) = o1;
        }
    }
}

// ------------------------- fused attention + combine + BN-stats (4-edge unrolled gather) ----------
// 1024 blocks x 32 nodes: smaller blocks shrink degree-variance tail.
// Uses shifted rowptr: e0 = rowptr[n-1] (0 for n==0), e1 = rowptr[n].
__global__ __launch_bounds__(256) void attn_combine_kernel(const float* __restrict__ We,
                                                           const float* __restrict__ Wb) {
    __shared__ float sWe[256];
    __shared__ float sWb[768];
    __shared__ float sS[8 * 256];
    __shared__ float sS2[8 * 256];
    int tid = threadIdx.x;
    sWe[tid] = We[tid];
    sWb[tid] = Wb[tid];
    sWb[tid + 256] = Wb[tid + 256];
    sWb[tid + 512] = Wb[tid + 512];
    __syncthreads();
    int warp = tid >> 5, lane = tid & 31;
    int head = lane >> 3;
    int ch = head * 64 + (lane & 7) * 8;

    float st[8], st2[8];
#pragma unroll
    for (int i = 0; i < 8; i++) { st[i] = 0.f; st2[i] = 0.f; }

    for (int it = 0; it < 4; it++) {
        int n = blockIdx.x * 32 + it * 8 + warp;

        float4 q0 = *reinterpret_cast<const float4*>(&g_q[n * 256 + ch]);
        float4 q1 = *reinterpret_cast<const float4*>(&g_q[n * 256 + ch + 4]);
        float qv[8] = {q0.x, q0.y, q0.z, q0.w, q1.x, q1.y, q1.z, q1.w};
        float qwe = 0.f;
#pragma unroll
        for (int i = 0; i < 8; i++) qwe += qv[i] * sWe[ch + i];
        qwe += __shfl_xor_sync(0xffffffffu, qwe, 4);
        qwe += __shfl_xor_sync(0xffffffffu, qwe, 2);
        qwe += __shfl_xor_sync(0xffffffffu, qwe, 1);

        int e0 = (n == 0) ? 0 : g_rowptr[n - 1];
        int e1 = g_rowptr[n];
        float acc[8];
#pragma unroll
        for (int i = 0; i < 8; i++) acc[i] = 0.f;
        float den = 0.f, exav = 0.f;

        int j = e0;
        for (; j + 3 < e1; j += 4) {
            int ss[4];
            float avv[4], pp[4], ee[4];
            float4 kk0[4], kk1[4], vv0[4], vv1[4];
#pragma unroll
            for (int u = 0; u < 4; u++) {
                ss[u] = g_esrc[j + u];
                avv[u] = g_eav[j + u];
            }
#pragma unroll
            for (int u = 0; u < 4; u++) {
                kk0[u] = *reinterpret_cast<const float4*>(&g_k[ss[u] * 256 + ch]);
                kk1[u] = *reinterpret_cast<const float4*>(&g_k[ss[u] * 256 + ch + 4]);
                vv0[u] = *reinterpret_cast<const float4*>(&g_v[ss[u] * 256 + ch]);
                vv1[u] = *reinterpret_cast<const float4*>(&g_v[ss[u] * 256 + ch + 4]);
            }
#pragma unroll
            for (int u = 0; u < 4; u++)
                pp[u] = qv[0] * kk0[u].x + qv[1] * kk0[u].y + qv[2] * kk0[u].z + qv[3] * kk0[u].w +
                        qv[4] * kk1[u].x + qv[5] * kk1[u].y + qv[6] * kk1[u].z + qv[7] * kk1[u].w;
#pragma unroll
            for (int u = 0; u < 4; u++) pp[u] += __shfl_xor_sync(0xffffffffu, pp[u], 4);
#pragma unroll
            for (int u = 0; u < 4; u++) pp[u] += __shfl_xor_sync(0xffffffffu, pp[u], 2);
#pragma unroll
            for (int u = 0; u < 4; u++) pp[u] += __shfl_xor_sync(0xffffffffu, pp[u], 1);
#pragma unroll
            for (int u = 0; u < 4; u++) ee[u] = expf((pp[u] + avv[u] * qwe) * 0.125f);
#pragma unroll
            for (int u = 0; u < 4; u++) {
                acc[0] += ee[u] * vv0[u].x;
                acc[1] += ee[u] * vv0[u].y;
                acc[2] += ee[u] * vv0[u].z;
                acc[3] += ee[u] * vv0[u].w;
                acc[4] += ee[u] * vv1[u].x;
                acc[5] += ee[u] * vv1[u].y;
                acc[6] += ee[u] * vv1[u].z;
                acc[7] += ee[u] * vv1[u].w;
                den += ee[u];
                exav += ee[u] * avv[u];
            }
        }
        for (; j < e1; j++) {
            int s = g_esrc[j];
            float av = g_eav[j];
            float4 k0 = *reinterpret_cast<const float4*>(&g_k[s * 256 + ch]);
            float4 k1 = *reinterpret_cast<const float4*>(&g_k[s * 256 + ch + 4]);
            float4 v0 = *reinterpret_cast<const float4*>(&g_v[s * 256 + ch]);
            float4 v1 = *reinterpret_cast<const float4*>(&g_v[s * 256 + ch + 4]);
            float p = qv[0] * k0.x + qv[1] * k0.y + qv[2] * k0.z + qv[3] * k0.w +
                      qv[4] * k1.x + qv[5] * k1.y + qv[6] * k1.z + qv[7] * k1.w;
            p += __shfl_xor_sync(0xffffffffu, p, 4);
            p += __shfl_xor_sync(0xffffffffu, p, 2);
            p += __shfl_xor_sync(0xffffffffu, p, 1);
            p += av * qwe;
            float ex = expf(p * 0.125f);  // scale=1/sqrt(64); max-shift cancels in ratio
            acc[0] += ex * v0.x; acc[1] += ex * v0.y; acc[2] += ex * v0.z; acc[3] += ex * v0.w;
            acc[4] += ex * v1.x; acc[5] += ex * v1.y; acc[6] += ex * v1.z; acc[7] += ex * v1.w;
            den += ex;
            exav += ex * av;
        }

        float inv = (den > 0.f) ? (1.f / den) : 0.f;  // isolated node -> out = 0
        float ov[8];
#pragma unroll
        for (int i = 0; i < 8; i++) ov[i] = (acc[i] + exav * sWe[ch + i]) * inv;

        float4 x0 = *reinterpret_cast<const float4*>(&g_xr[n * 256 + ch]);
        float4 x1 = *reinterpret_cast<const float4*>(&g_xr[n * 256 + ch + 4]);
        float xv[8] = {x0.x, x0.y, x0.z, x0.w, x1.x, x1.y, x1.z, x1.w};
        float p = 0.f;
#pragma unroll
        for (int i = 0; i < 8; i++)
            p += ov[i] * sWb[ch + i] + xv[i] * sWb[256 + ch + i] + (ov[i] - xv[i]) * sWb[512 + ch + i];
#pragma unroll
        for (int off = 16; off; off >>= 1) p += __shfl_xor_sync(0xffffffffu, p, off);
        float beta = 1.f / (1.f + expf(-p));
        float r[8];
#pragma unroll
        for (int i = 0; i < 8; i++) {
            r[i] = beta * xv[i] + (1.f - beta) * ov[i];
            st[i] += r[i];
            st2[i] += r[i] * r[i];
        }
        *reinterpret_cast<float4*>(&g_h[n * 256 + ch]) = make_float4(r[0], r[1], r[2], r[3]);
        *reinterpret_cast<float4*>(&g_h[n * 256 + ch + 4]) = make_float4(r[4], r[5], r[6], r[7]);
    }

#pragma unroll
    for (int i = 0; i < 8; i++) {
        sS[warp * 256 + ch + i] = st[i];
        sS2[warp * 256 + ch + i] = st2[i];
    }
    __syncthreads();
    float ts = 0.f, ts2 = 0.f;
#pragma unroll
    for (int w = 0; w < 8; w++) {
        ts += sS[w * 256 + tid];
        ts2 += sS2[w * 256 + tid];
    }
    atomicAdd(&g_colstats[tid], ts);
    atomicAdd(&g_colstats[256 + tid], ts2);
}

// ------------------------- BN apply + ELU (layer 1: float4-vectorized) -------------------------
__global__ void bn_apply_l1_kernel(const float* __restrict__ gamma, const float* __restrict__ beta) {
    int i = blockIdx.x * blockDim.x + threadIdx.x;   // over NN*64 float4s
    if (i >= NN * 64) return;
    int n = i >> 6, d4 = (i & 63) * 4;
    float4 hv = *reinterpret_cast<const float4*>(&g_h[n * 256 + d4]);
    float4 cs = *reinterpret_cast<const float4*>(&g_colstats[d4]);
    float4 cs2 = *reinterpret_cast<const float4*>(&g_colstats[256 + d4]);
    float4 gm = *reinterpret_cast<const float4*>(&gamma[d4]);
    float4 bt = *reinterpret_cast<const float4*>(&beta[d4]);
    float h[4] = {hv.x, hv.y, hv.z, hv.w};
    float s[4] = {cs.x, cs.y, cs.z, cs.w};
    float s2[4] = {cs2.x, cs2.y, cs2.z, cs2.w};
    float g[4] = {gm.x, gm.y, gm.z, gm.w};
    float b[4] = {bt.x, bt.y, bt.z, bt.w};
    float r[4];
#pragma unroll
    for (int t = 0; t < 4; t++) {
        float mu = s[t] * (1.f / NN);
        float var = s2[t] * (1.f / NN) - mu * mu;
        float y = g[t] * (h[t] - mu) * rsqrtf(var + BN_EPS) + b[t];
        r[t] = y > 0.f ? y : expm1f(y);
    }
    *reinterpret_cast<float4*>(&g_h[n * 256 + d4]) = make_float4(r[0], r[1], r[2], r[3]);
    g_ht[permA(n, d4 + 0)] = f2tf32(r[0]);
    g_ht[permA(n, d4 + 1)] = f2tf32(r[1]);
    g_ht[permA(n, d4 + 2)] = f2tf32(r[2]);
    g_ht[permA(n, d4 + 3)] = f2tf32(r[3]);
}

// ------------------------- BN apply + ELU + gate (layer 2) -------------------------
__global__ void bn_apply_gate_kernel(const float* __restrict__ gamma, const float* __restrict__ beta,
                                     const int* __restrict__ batch, const float* __restrict__ gW,
                                     const float* __restrict__ gb) {
    __shared__ float sgW[256];
    int tid = threadIdx.x;
    sgW[tid] = gW[tid];
    __syncthreads();
    int warp = tid >> 5, lane = tid & 31;
    int n = blockIdx.x * 8 + warp;
    if (n >= NN) return;
    int ch = lane * 8;
    float p = 0.f;
    float r[8];
#pragma unroll
    for (int i = 0; i < 8; i++) {
        int d = ch + i;
        float mu = g_colstats[d] * (1.f / NN);
        float var = g_colstats[256 + d] * (1.f / NN) - mu * mu;
        float y = gamma[d] * (g_h[n * 256 + d] - mu) * rsqrtf(var + BN_EPS) + beta[d];
        r[i] = y > 0.f ? y : expm1f(y);
        p += r[i] * sgW[d];
    }
    *reinterpret_cast<float4*>(&g_h[n * 256 + ch]) = make_float4(r[0], r[1], r[2], r[3]);
    *reinterpret_cast<float4*>(&g_h[n * 256 + ch + 4]) = make_float4(r[4], r[5], r[6], r[7]);
#pragma unroll
    for (int off = 16; off; off >>= 1) p += __shfl_xor_sync(0xffffffffu, p, off);
    if (lane == 0) {
        float ex = expf(p + gb[0]);
        g_gate[n] = ex;
        atomicAdd(&g_gden[batch[n]], ex);
    }
}

// ------------------------- readout: segment-aware pooling (256 blocks x 128 nodes) ----------
__global__ __launch_bounds__(256) void pool_seg_kernel(const int* __restrict__ batch) {
    __shared__ float sw[128];
    __shared__ int sbt[128];
    int tid = threadIdx.x;
    int n0 = blockIdx.x * 128;
    if (tid < 128) {
        int n = n0 + tid;
        int g = batch[n];
        sbt[tid] = g;
        sw[tid] = g_gate[n] / g_gden[g];
    }
    __syncthreads();
    float acc = 0.f;
    int curg = sbt[0];
    for (int i = 0; i < 128; i++) {
        int g = sbt[i];
        if (g != curg) {
            atomicAdd(&g_hG[curg * 256 + tid], acc);
            acc = 0.f;
            curg = g;
        }
        acc += sw[i] * g_h[(n0 + i) * 256 + tid];
    }
    atomicAdd(&g_hG[curg * 256 + tid], acc);
}

__global__ void final_kernel(const float* __restrict__ dW, const float* __restrict__ db,
                             const float* __restrict__ ob, float* __restrict__ out) {
    __shared__ float red[256];
    int g = blockIdx.x, t = threadIdx.x;
    red[t] = g_hG[g * 256 + t] * dW[t];
    __syncthreads();
    for (int s = 128; s > 0; s >>= 1) {
        if (t < s) red[t] += red[t + s];
        __syncthreads();
    }
    if (t == 0) out[g] = red[0] + db[0] + ob[0];
}

// ------------------------- launcher -------------------------
extern "C" void kernel_launch(void* const* d_in, const int* in_sizes, int n_in,
                              void* d_out, int out_size) {
    const float* x     = (const float*)d_in[0];
    const int*   ei    = (const int*)d_in[1];
    const float* ea    = (const float*)d_in[2];
    const int*   batch = (const int*)d_in[3];
    const float* encW  = (const float*)d_in[4];
    const float* encb  = (const float*)d_in[5];
    const float* Wq    = (const float*)d_in[6];
    const float* bq    = (const float*)d_in[7];
    const float* Wk    = (const float*)d_in[8];
    const float* bk    = (const float*)d_in[9];
    const float* Wv    = (const float*)d_in[10];
    const float* bv    = (const float*)d_in[11];
    const float* We    = (const float*)d_in[12];
    const float* Wskip = (const float*)d_in[13];
    const float* bskip = (const float*)d_in[14];
    const float* Wbeta = (const float*)d_in[15];
    const float* bng   = (const float*)d_in[16];
    const float* bnb   = (const float*)d_in[17];
    const float* gW    = (const float*)d_in[18];
    const float* gb    = (const float*)d_in[19];
    const float* dW    = (const float*)d_in[20];
    const float* db    = (const float*)d_in[21];
    const float* ob    = (const float*)d_in[22];
    float* out = (float*)d_out;

    const int* src = ei;
    const int* dst = ei + EE;

    const int TPB = 256;

    prep_w_kernel<<<dim3(DD * DD / TPB, 8), TPB>>>(Wq, Wk, Wv, Wskip);
    zero_prep_kernel<<<NN / TPB, TPB>>>();
    deg_hist_kernel<<<EE / TPB, TPB>>>(dst);
    scan_kernel<<<1, 1024>>>();
    scatter_kernel<<<EE / TPB, TPB>>>(src, dst, ea);
    encoder_kernel<<<(NN * 64) / TPB, TPB>>>(x, encW, encb);

    for (int l = 0; l < 2; l++) {
        mma_gemm4<<<dim3(8, 256), TPB>>>(bq, bk, bv, bskip, l);
        attn_combine_kernel<<<1024, TPB>>>(We + l * DD, Wbeta + l * 3 * DD);
        if (l == 0) {
            bn_apply_l1_kernel<<<(NN * 64) / TPB, TPB>>>(bng, bnb);
        } else {
            bn_apply_gate_kernel<<<NN / 8, TPB>>>(bng + DD, bnb + DD, batch, gW, gb);
        }
    }

    pool_seg_kernel<<<NN / 128, TPB>>>(batch);
    final_kernel<<<GG, TPB>>>(dW, db, ob, out);
}

// round 17
// speedup vs baseline: 2.0788x; 1.0393x over previous
#include <cuda_runtime.h>
#include <math.h>
#include <stdint.h>

#define NN 32768
#define EE 262144
#define DD 256
#define HH 4
#define GG 32
#define BN_EPS 1e-5f

// ------------------------- scratch (device globals) -------------------------
__device__ float g_h[NN * DD];
__device__ uint32_t g_ht[NN * DD];     // tf32 copy of g_h, PERMUTED to A-fragment order
__device__ uint32_t g_wt[8 * DD * DD]; // tf32 weights, PERMUTED to B-fragment order
__device__ float g_q[NN * DD];
__device__ float g_k[NN * DD];
__device__ float g_v[NN * DD];
__device__ float g_xr[NN * DD];
__device__ float g_colstats[2 * DD];
__device__ float g_gate[NN];
__device__ float g_gden[GG];
__device__ float g_hG[GG * DD];
// CSR by dst. scatter consumes rowptr in place; post-scatter rowptr[d] = orig_start[d+1].
__device__ int g_rowptr[NN + 1];
__device__ int g_cnt[NN];
__device__ int g_bsum[32];
__device__ int g_esrc[EE];
__device__ float g_eav[EE];

__device__ __forceinline__ uint32_t f2tf32(float f) {
    uint32_t r;
    asm("cvt.rna.tf32.f32 %0, %1;" : "=r"(r) : "f"(f));
    return r;
}

// A-fragment permutation: index = ((rg*32 + kb)*32 + lane)*4 + elem.
__device__ __forceinline__ int permA(int n, int d) {
    int rg = n >> 4, kb = d >> 3;
    int lane = (n & 7) * 4 + (d & 3);
    int elem = ((n >> 3) & 1) + ((d >> 2) & 1) * 2;
    return ((rg * 32 + kb) * 32 + lane) * 4 + elem;
}

// ------------------------- merged zero kernel (cnt + readout) -------------------------
__global__ void zero_prep_kernel() {
    int i = blockIdx.x * blockDim.x + threadIdx.x;
    if (i < NN) g_cnt[i] = 0;
    if (i < GG * DD) g_hG[i] = 0.f;
    if (i < GG) g_gden[i] = 0.f;
}

// ------------------------- CSR build -------------------------
__global__ void deg_hist_kernel(const int* __restrict__ dst) {
    int e = blockIdx.x * blockDim.x + threadIdx.x;
    if (e < EE) atomicAdd(&g_cnt[dst[e]], 1);
}

// two-level scan: 32 blocks x 1024 local inclusive scan + block totals
__global__ __launch_bounds__(1024) void scan_local_kernel() {
    __shared__ int swarp[32];
    int tid = threadIdx.x;
    int lane = tid & 31, w = tid >> 5;
    int base = blockIdx.x * 1024;
    int x = g_cnt[base + tid];
#pragma unroll
    for (int o = 1; o < 32; o <<= 1) {
        int y = __shfl_up_sync(0xffffffffu, x, o);
        if (lane >= o) x += y;
    }
    if (lane == 31) swarp[w] = x;
    __syncthreads();
    if (w == 0) {
        int y = swarp[lane];
#pragma unroll
        for (int o = 1; o < 32; o <<= 1) {
            int z = __shfl_up_sync(0xffffffffu, y, o);
            if (lane >= o) y += z;
        }
        swarp[lane] = y;
    }
    __syncthreads();
    int incl = x + (w > 0 ? swarp[w - 1] : 0);
    g_rowptr[base + tid + 1] = incl;
    if (tid == 1023) g_bsum[blockIdx.x] = incl;
}

__global__ __launch_bounds__(1024) void scan_fixup_kernel() {
    __shared__ int soff;
    int tid = threadIdx.x;
    if (tid == 0) {
        int o = 0;
        for (int j = 0; j < (int)blockIdx.x; j++) o += g_bsum[j];
        soff = o;
    }
    __syncthreads();
    int base = blockIdx.x * 1024;
    if (blockIdx.x > 0) g_rowptr[base + tid + 1] += soff;
    if (blockIdx.x == 0 && tid == 0) g_rowptr[0] = 0;
}

// Consumes g_rowptr in place; scan rebuilds it each launch (replay-idempotent).
__global__ void scatter_kernel(const int* __restrict__ src, const int* __restrict__ dst,
                               const float* __restrict__ ea) {
    int e = blockIdx.x * blockDim.x + threadIdx.x;
    if (e >= EE) return;
    int d = dst[e];
    int pos = atomicAdd(&g_rowptr[d], 1);
    g_esrc[pos] = src[e];
    g_eav[pos] = ea[e];
}

// ------------------------- weight prep: tf32 + B-fragment permutation -------------------------
__global__ void prep_w_kernel(const float* __restrict__ Wq, const float* __restrict__ Wk,
                              const float* __restrict__ Wv, const float* __restrict__ Ws) {
    int m = blockIdx.y;            // 0..7 : layer*4 + which
    int i = blockIdx.x * blockDim.x + threadIdx.x;   // 0..65535
    int l = m >> 2, w = m & 3;
    const float* S = ((w == 0) ? Wq : (w == 1) ? Wk : (w == 2) ? Wv : Ws) + (size_t)l * DD * DD;
    int kb = i >> 11;
    int rem = i & 2047;
    int nb = rem >> 8;
    int o = rem & 255;
    int pairidx = (o >> 7) & 1;
    int lq = (o >> 2) & 31;
    int e = o & 3;
    int fn = pairidx * 2 + (e >> 1);
    int half = e & 1;
    int gid = lq >> 2, tig = lq & 3;
    int k = kb * 8 + tig + half * 4;
    int n = nb * 32 + fn * 8 + gid;
    g_wt[(size_t)m * 65536 + i] = f2tf32(S[k * 256 + n]);
}

// ------------------------- encoder (float4-vectorized; writes permuted tf32 copy) ----------
__global__ void encoder_kernel(const float* __restrict__ x,
                               const float* __restrict__ W,
                               const float* __restrict__ b) {
    int i = blockIdx.x * blockDim.x + threadIdx.x;   // over NN*64 float4s
    if (i >= NN * 64) return;
    int n = i >> 6, d4 = (i & 63) * 4;
    float x0 = x[n * 2], x1 = x[n * 2 + 1];
    float4 w0 = *reinterpret_cast<const float4*>(&W[d4]);
    float4 w1 = *reinterpret_cast<const float4*>(&W[DD + d4]);
    float4 bb = *reinterpret_cast<const float4*>(&b[d4]);
    float4 h;
    h.x = x0 * w0.x + x1 * w1.x + bb.x;
    h.y = x0 * w0.y + x1 * w1.y + bb.y;
    h.z = x0 * w0.z + x1 * w1.z + bb.z;
    h.w = x0 * w0.w + x1 * w1.w + bb.w;
    *reinterpret_cast<float4*>(&g_h[n * 256 + d4]) = h;
    g_ht[permA(n, d4 + 0)] = f2tf32(h.x);
    g_ht[permA(n, d4 + 1)] = f2tf32(h.y);
    g_ht[permA(n, d4 + 2)] = f2tf32(h.z);
    g_ht[permA(n, d4 + 3)] = f2tf32(h.w);
}

// ------------------------- TF32 mma.sync GEMM, 3-stage pipeline, LDS.128 fragments ----------
__device__ __forceinline__ void cp16(uint32_t s, const void* g) {
    asm volatile("cp.async.ca.shared.global [%0], [%1], 16;" :: "r"(s), "l"(g));
}

__device__ __forceinline__ void mma8(float* c, const uint32_t* a, const uint32_t* b) {
    asm volatile(
        "mma.sync.aligned.m16n8k8.row.col.f32.tf32.tf32.f32 "
        "{%0,%1,%2,%3}, {%4,%5,%6,%7}, {%8,%9}, {%0,%1,%2,%3};"
        : "+f"(c[0]), "+f"(c[1]), "+f"(c[2]), "+f"(c[3])
        : "r"(a[0]), "r"(a[1]), "r"(a[2]), "r"(a[3]), "r"(b[0]), "r"(b[1]));
}

__global__ __launch_bounds__(256, 2) void mma_gemm4(const float* __restrict__ bq,
                                                    const float* __restrict__ bk,
                                                    const float* __restrict__ bv,
                                                    const float* __restrict__ bs,
                                                    int layer) {
    __shared__ uint32_t As[3][2048];
    __shared__ uint32_t Bs[3][2048];

    // fold colstats zeroing into the GEMM (runs between prior BN-read and next attn-add)
    if (blockIdx.x == 0 && blockIdx.y == 0) {
        if (threadIdx.x < 256) {
            g_colstats[threadIdx.x] = 0.f;
            g_colstats[256 + threadIdx.x] = 0.f;
        }
    }

    int mat = blockIdx.x >> 1;
    int bn = (blockIdx.x & 1) * 128;
    int bm = blockIdx.y * 128;
    const float* bias = ((mat == 0) ? bq : (mat == 1) ? bk : (mat == 2) ? bv : bs) + layer * DD;
    float* Cm = (mat == 0) ? g_q : (mat == 1) ? g_k : (mat == 2) ? g_v : g_xr;
    const uint32_t* A = g_ht;
    const uint32_t* B = g_wt + (size_t)(layer * 4 + mat) * 65536;

    int tid = threadIdx.x;
    int warp = tid >> 5, lane = tid & 31;
    int gid = lane >> 2, tig = lane & 3;
    int warp_m = (warp & 1) * 64;
    int warp_n = (warp >> 1) * 32;
    int rg_w = (warp & 1) * 4;
    int nb_w = warp >> 1;
    int rgbase = bm >> 4;
    int nbbase = bn >> 5;

    float acc[4][4][4];
#pragma unroll
    for (int i = 0; i < 4; i++)
#pragma unroll
        for (int j = 0; j < 4; j++)
#pragma unroll
            for (int r = 0; r < 4; r++) acc[i][j][r] = 0.f;

    uint32_t as_base = (uint32_t)__cvta_generic_to_shared(&As[0][0]);
    uint32_t bs_base = (uint32_t)__cvta_generic_to_shared(&Bs[0][0]);

    auto load_tiles = [&](int buf, int k0) {
        int kb0 = k0 >> 3;
#pragma unroll
        for (int i = 0; i < 2; i++) {
            int slot = tid + i * 256;
            int rg_i = slot >> 6, kb_i = (slot >> 5) & 1, ch = slot & 31;
            cp16(as_base + (uint32_t)(buf * 2048 + (rg_i * 2 + kb_i) * 128 + ch * 4) * 4u,
                 &A[(size_t)((rgbase + rg_i) * 32 + kb0 + kb_i) * 128 + ch * 4]);
            int kb_j = slot >> 8, nb_j = (slot >> 6) & 3, ch2 = slot & 63;
            cp16(bs_base + (uint32_t)(buf * 2048 + (kb_j * 4 + nb_j) * 256 + ch2 * 4) * 4u,
                 &B[(size_t)((kb0 + kb_j) * 8 + nbbase + nb_j) * 256 + ch2 * 4]);
        }
    };

    load_tiles(0, 0);
    asm volatile("cp.async.commit_group;");
    load_tiles(1, 16);
    asm volatile("cp.async.commit_group;");

    for (int it = 0; it < 16; it++) {
        asm volatile("cp.async.wait_group 1;");
        __syncthreads();
        if (it + 2 < 16) load_tiles((it + 2) % 3, (it + 2) * 16);
        asm volatile("cp.async.commit_group;");

        int buf = it % 3;
#pragma unroll
        for (int ksb = 0; ksb < 2; ksb++) {
            const uint4* bp = reinterpret_cast<const uint4*>(
                &Bs[buf][(ksb * 4 + nb_w) * 256 + lane * 4]);
            uint4 b01 = bp[0];
            uint4 b23 = bp[32];
            uint32_t bfr[4][2] = {{b01.x, b01.y}, {b01.z, b01.w},
                                  {b23.x, b23.y}, {b23.z, b23.w}};
#pragma unroll
            for (int fm = 0; fm < 4; fm++) {
                uint4 a = *reinterpret_cast<const uint4*>(
                    &As[buf][((rg_w + fm) * 2 + ksb) * 128 + lane * 4]);
                uint32_t afr[4] = {a.x, a.y, a.z, a.w};
#pragma unroll
                for (int fn = 0; fn < 4; fn++) mma8(acc[fm][fn], afr, bfr[fn]);
            }
        }
    }

#pragma unroll
    for (int fm = 0; fm < 4; fm++) {
        int row = bm + warp_m + fm * 16 + gid;
#pragma unroll
        for (int fn = 0; fn < 4; fn++) {
            int col = bn + warp_n + fn * 8 + tig * 2;
            float b0 = bias[col], b1 = bias[col + 1];
            float2 o0 = make_float2(acc[fm][fn][0] + b0, acc[fm][fn][1] + b1);
            float2 o1 = make_float2(acc[fm][fn][2] + b0, acc[fm][fn][3] + b1);
            *reinterpret_cast<float2*>(&Cm[(size_t)row * 256 + col]) = o0;
            *reinterpret_cast<float2*>(&Cm[(size_t)(row + 8) * 256 + col]) = o1;
        }
    }
}

// ------------------------- fused attention + combine + BN-stats (4-edge unrolled gather) ----------
// 1024 blocks x 32 nodes. Uses shifted rowptr: e0 = rowptr[n-1] (0 for n==0), e1 = rowptr[n].
__global__ __launch_bounds__(256) void attn_combine_kernel(const float* __restrict__ We,
                                                           const float* __restrict__ Wb) {
    __shared__ float sWe[256];
    __shared__ float sWb[768];
    __shared__ float sS[8 * 256];
    __shared__ float sS2[8 * 256];
    int tid = threadIdx.x;
    sWe[tid] = We[tid];
    sWb[tid] = Wb[tid];
    sWb[tid + 256] = Wb[tid + 256];
    sWb[tid + 512] = Wb[tid + 512];
    __syncthreads();
    int warp = tid >> 5, lane = tid & 31;
    int head = lane >> 3;
    int ch = head * 64 + (lane & 7) * 8;

    float st[8], st2[8];
#pragma unroll
    for (int i = 0; i < 8; i++) { st[i] = 0.f; st2[i] = 0.f; }

    for (int it = 0; it < 4; it++) {
        int n = blockIdx.x * 32 + it * 8 + warp;

        float4 q0 = *reinterpret_cast<const float4*>(&g_q[n * 256 + ch]);
        float4 q1 = *reinterpret_cast<const float4*>(&g_q[n * 256 + ch + 4]);
        float qv[8] = {q0.x, q0.y, q0.z, q0.w, q1.x, q1.y, q1.z, q1.w};
        float qwe = 0.f;
#pragma unroll
        for (int i = 0; i < 8; i++) qwe += qv[i] * sWe[ch + i];
        qwe += __shfl_xor_sync(0xffffffffu, qwe, 4);
        qwe += __shfl_xor_sync(0xffffffffu, qwe, 2);
        qwe += __shfl_xor_sync(0xffffffffu, qwe, 1);

        int e0 = (n == 0) ? 0 : g_rowptr[n - 1];
        int e1 = g_rowptr[n];
        float acc[8];
#pragma unroll
        for (int i = 0; i < 8; i++) acc[i] = 0.f;
        float den = 0.f, exav = 0.f;

        int j = e0;
        for (; j + 3 < e1; j += 4) {
            int ss[4];
            float avv[4], pp[4], ee[4];
            float4 kk0[4], kk1[4], vv0[4], vv1[4];
#pragma unroll
            for (int u = 0; u < 4; u++) {
                ss[u] = g_esrc[j + u];
                avv[u] = g_eav[j + u];
            }
#pragma unroll
            for (int u = 0; u < 4; u++) {
                kk0[u] = *reinterpret_cast<const float4*>(&g_k[ss[u] * 256 + ch]);
                kk1[u] = *reinterpret_cast<const float4*>(&g_k[ss[u] * 256 + ch + 4]);
                vv0[u] = *reinterpret_cast<const float4*>(&g_v[ss[u] * 256 + ch]);
                vv1[u] = *reinterpret_cast<const float4*>(&g_v[ss[u] * 256 + ch + 4]);
            }
#pragma unroll
            for (int u = 0; u < 4; u++)
                pp[u] = qv[0] * kk0[u].x + qv[1] * kk0[u].y + qv[2] * kk0[u].z + qv[3] * kk0[u].w +
                        qv[4] * kk1[u].x + qv[5] * kk1[u].y + qv[6] * kk1[u].z + qv[7] * kk1[u].w;
#pragma unroll
            for (int u = 0; u < 4; u++) pp[u] += __shfl_xor_sync(0xffffffffu, pp[u], 4);
#pragma unroll
            for (int u = 0; u < 4; u++) pp[u] += __shfl_xor_sync(0xffffffffu, pp[u], 2);
#pragma unroll
            for (int u = 0; u < 4; u++) pp[u] += __shfl_xor_sync(0xffffffffu, pp[u], 1);
#pragma unroll
            for (int u = 0; u < 4; u++) ee[u] = expf((pp[u] + avv[u] * qwe) * 0.125f);
#pragma unroll
            for (int u = 0; u < 4; u++) {
                acc[0] += ee[u] * vv0[u].x;
                acc[1] += ee[u] * vv0[u].y;
                acc[2] += ee[u] * vv0[u].z;
                acc[3] += ee[u] * vv0[u].w;
                acc[4] += ee[u] * vv1[u].x;
                acc[5] += ee[u] * vv1[u].y;
                acc[6] += ee[u] * vv1[u].z;
                acc[7] += ee[u] * vv1[u].w;
                den += ee[u];
                exav += ee[u] * avv[u];
            }
        }
        for (; j < e1; j++) {
            int s = g_esrc[j];
            float av = g_eav[j];
            float4 k0 = *reinterpret_cast<const float4*>(&g_k[s * 256 + ch]);
            float4 k1 = *reinterpret_cast<const float4*>(&g_k[s * 256 + ch + 4]);
            float4 v0 = *reinterpret_cast<const float4*>(&g_v[s * 256 + ch]);
            float4 v1 = *reinterpret_cast<const float4*>(&g_v[s * 256 + ch + 4]);
            float p = qv[0] * k0.x + qv[1] * k0.y + qv[2] * k0.z + qv[3] * k0.w +
                      qv[4] * k1.x + qv[5] * k1.y + qv[6] * k1.z + qv[7] * k1.w;
            p += __shfl_xor_sync(0xffffffffu, p, 4);
            p += __shfl_xor_sync(0xffffffffu, p, 2);
            p += __shfl_xor_sync(0xffffffffu, p, 1);
            p += av * qwe;
            float ex = expf(p * 0.125f);  // scale=1/sqrt(64); max-shift cancels in ratio
            acc[0] += ex * v0.x; acc[1] += ex * v0.y; acc[2] += ex * v0.z; acc[3] += ex * v0.w;
            acc[4] += ex * v1.x; acc[5] += ex * v1.y; acc[6] += ex * v1.z; acc[7] += ex * v1.w;
            den += ex;
            exav += ex * av;
        }

        float inv = (den > 0.f) ? (1.f / den) : 0.f;  // isolated node -> out = 0
        float ov[8];
#pragma unroll
        for (int i = 0; i < 8; i++) ov[i] = (acc[i] + exav * sWe[ch + i]) * inv;

        float4 x0 = *reinterpret_cast<const float4*>(&g_xr[n * 256 + ch]);
        float4 x1 = *reinterpret_cast<const float4*>(&g_xr[n * 256 + ch + 4]);
        float xv[8] = {x0.x, x0.y, x0.z, x0.w, x1.x, x1.y, x1.z, x1.w};
        float p = 0.f;
#pragma unroll
        for (int i = 0; i < 8; i++)
            p += ov[i] * sWb[ch + i] + xv[i] * sWb[256 + ch + i] + (ov[i] - xv[i]) * sWb[512 + ch + i];
#pragma unroll
        for (int off = 16; off; off >>= 1) p += __shfl_xor_sync(0xffffffffu, p, off);
        float beta = 1.f / (1.f + expf(-p));
        float r[8];
#pragma unroll
        for (int i = 0; i < 8; i++) {
            r[i] = beta * xv[i] + (1.f - beta) * ov[i];
            st[i] += r[i];
            st2[i] += r[i] * r[i];
        }
        *reinterpret_cast<float4*>(&g_h[n * 256 + ch]) = make_float4(r[0], r[1], r[2], r[3]);
        *reinterpret_cast<float4*>(&g_h[n * 256 + ch + 4]) = make_float4(r[4], r[5], r[6], r[7]);
    }

#pragma unroll
    for (int i = 0; i < 8; i++) {
        sS[warp * 256 + ch + i] = st[i];
        sS2[warp * 256 + ch + i] = st2[i];
    }
    __syncthreads();
    float ts = 0.f, ts2 = 0.f;
#pragma unroll
    for (int w = 0; w < 8; w++) {
        ts += sS[w * 256 + tid];
        ts2 += sS2[w * 256 + tid];
    }
    atomicAdd(&g_colstats[tid], ts);
    atomicAdd(&g_colstats[256 + tid], ts2);
}

// ------------------------- BN apply + ELU (layer 1: float4-vectorized) -------------------------
__global__ void bn_apply_l1_kernel(const float* __restrict__ gamma, const float* __restrict__ beta) {
    int i = blockIdx.x * blockDim.x + threadIdx.x;   // over NN*64 float4s
    if (i >= NN * 64) return;
    int n = i >> 6, d4 = (i & 63) * 4;
    float4 hv = *reinterpret_cast<const float4*>(&g_h[n * 256 + d4]);
    float4 cs = *reinterpret_cast<const float4*>(&g_colstats[d4]);
    float4 cs2 = *reinterpret_cast<const float4*>(&g_colstats[256 + d4]);
    float4 gm = *reinterpret_cast<const float4*>(&gamma[d4]);
    float4 bt = *reinterpret_cast<const float4*>(&beta[d4]);
    float h[4] = {hv.x, hv.y, hv.z, hv.w};
    float s[4] = {cs.x, cs.y, cs.z, cs.w};
    float s2[4] = {cs2.x, cs2.y, cs2.z, cs2.w};
    float g[4] = {gm.x, gm.y, gm.z, gm.w};
    float b[4] = {bt.x, bt.y, bt.z, bt.w};
    float r[4];
#pragma unroll
    for (int t = 0; t < 4; t++) {
        float mu = s[t] * (1.f / NN);
        float var = s2[t] * (1.f / NN) - mu * mu;
        float y = g[t] * (h[t] - mu) * rsqrtf(var + BN_EPS) + b[t];
        r[t] = y > 0.f ? y : expm1f(y);
    }
    *reinterpret_cast<float4*>(&g_h[n * 256 + d4]) = make_float4(r[0], r[1], r[2], r[3]);
    g_ht[permA(n, d4 + 0)] = f2tf32(r[0]);
    g_ht[permA(n, d4 + 1)] = f2tf32(r[1]);
    g_ht[permA(n, d4 + 2)] = f2tf32(r[2]);
    g_ht[permA(n, d4 + 3)] = f2tf32(r[3]);
}

// ------------------------- BN apply + ELU + gate (layer 2) -------------------------
__global__ void bn_apply_gate_kernel(const float* __restrict__ gamma, const float* __restrict__ beta,
                                     const int* __restrict__ batch, const float* __restrict__ gW,
                                     const float* __restrict__ gb) {
    __shared__ float sgW[256];
    int tid = threadIdx.x;
    sgW[tid] = gW[tid];
    __syncthreads();
    int warp = tid >> 5, lane = tid & 31;
    int n = blockIdx.x * 8 + warp;
    if (n >= NN) return;
    int ch = lane * 8;
    float p = 0.f;
    float r[8];
#pragma unroll
    for (int i = 0; i < 8; i++) {
        int d = ch + i;
        float mu = g_colstats[d] * (1.f / NN);
        float var = g_colstats[256 + d] * (1.f / NN) - mu * mu;
        float y = gamma[d] * (g_h[n * 256 + d] - mu) * rsqrtf(var + BN_EPS) + beta[d];
        r[i] = y > 0.f ? y : expm1f(y);
        p += r[i] * sgW[d];
    }
    *reinterpret_cast<float4*>(&g_h[n * 256 + ch]) = make_float4(r[0], r[1], r[2], r[3]);
    *reinterpret_cast<float4*>(&g_h[n * 256 + ch + 4]) = make_float4(r[4], r[5], r[6], r[7]);
#pragma unroll
    for (int off = 16; off; off >>= 1) p += __shfl_xor_sync(0xffffffffu, p, off);
    if (lane == 0) {
        float ex = expf(p + gb[0]);
        g_gate[n] = ex;
        atomicAdd(&g_gden[batch[n]], ex);
    }
}

// ------------------------- readout: segment-aware pooling (256 blocks x 128 nodes) ----------
__global__ __launch_bounds__(256) void pool_seg_kernel(const int* __restrict__ batch) {
    __shared__ float sw[128];
    __shared__ int sbt[128];
    int tid = threadIdx.x;
    int n0 = blockIdx.x * 128;
    if (tid < 128) {
        int n = n0 + tid;
        int g = batch[n];
        sbt[tid] = g;
        sw[tid] = g_gate[n] / g_gden[g];
    }
    __syncthreads();
    float acc = 0.f;
    int curg = sbt[0];
    for (int i = 0; i < 128; i++) {
        int g = sbt[i];
        if (g != curg) {
            atomicAdd(&g_hG[curg * 256 + tid], acc);
            acc = 0.f;
            curg = g;
        }
        acc += sw[i] * g_h[(n0 + i) * 256 + tid];
    }
    atomicAdd(&g_hG[curg * 256 + tid], acc);
}

__global__ void final_kernel(const float* __restrict__ dW, const float* __restrict__ db,
                             const float* __restrict__ ob, float* __restrict__ out) {
    __shared__ float red[256];
    int g = blockIdx.x, t = threadIdx.x;
    red[t] = g_hG[g * 256 + t] * dW[t];
    __syncthreads();
    for (int s = 128; s > 0; s >>= 1) {
        if (t < s) red[t] += red[t + s];
        __syncthreads();
    }
    if (t == 0) out[g] = red[0] + db[0] + ob[0];
}

// ------------------------- launcher -------------------------
extern "C" void kernel_launch(void* const* d_in, const int* in_sizes, int n_in,
                              void* d_out, int out_size) {
    const float* x     = (const float*)d_in[0];
    const int*   ei    = (const int*)d_in[1];
    const float* ea    = (const float*)d_in[2];
    const int*   batch = (const int*)d_in[3];
    const float* encW  = (const float*)d_in[4];
    const float* encb  = (const float*)d_in[5];
    const float* Wq    = (const float*)d_in[6];
    const float* bq    = (const float*)d_in[7];
    const float* Wk    = (const float*)d_in[8];
    const float* bk    = (const float*)d_in[9];
    const float* Wv    = (const float*)d_in[10];
    const float* bv    = (const float*)d_in[11];
    const float* We    = (const float*)d_in[12];
    const float* Wskip = (const float*)d_in[13];
    const float* bskip = (const float*)d_in[14];
    const float* Wbeta = (const float*)d_in[15];
    const float* bng   = (const float*)d_in[16];
    const float* bnb   = (const float*)d_in[17];
    const float* gW    = (const float*)d_in[18];
    const float* gb    = (const float*)d_in[19];
    const float* dW    = (const float*)d_in[20];
    const float* db    = (const float*)d_in[21];
    const float* ob    = (const float*)d_in[22];
    float* out = (float*)d_out;

    const int* src = ei;
    const int* dst = ei + EE;

    const int TPB = 256;

    prep_w_kernel<<<dim3(DD * DD / TPB, 8), TPB>>>(Wq, Wk, Wv, Wskip);
    zero_prep_kernel<<<NN / TPB, TPB>>>();
    deg_hist_kernel<<<EE / TPB, TPB>>>(dst);
    scan_local_kernel<<<32, 1024>>>();
    scan_fixup_kernel<<<32, 1024>>>();
    scatter_kernel<<<EE / TPB, TPB>>>(src, dst, ea);
    encoder_kernel<<<(NN * 64) / TPB, TPB>>>(x, encW, encb);

    for (int l = 0; l < 2; l++) {
        mma_gemm4<<<dim3(8, 256), TPB>>>(bq, bk, bv, bskip, l);
        attn_combine_kernel<<<1024, TPB>>>(We + l * DD, Wbeta + l * 3 * DD);
        if (l == 0) {
            bn_apply_l1_kernel<<<(NN * 64) / TPB, TPB>>>(bng, bnb);
        } else {
            bn_apply_gate_kernel<<<NN / 8, TPB>>>(bng + DD, bnb + DD, batch, gW, gb);
        }
    }

    pool_seg_kernel<<<NN / 128, TPB>>>(batch);
    final_kernel<<<GG, TPB>>>(dW, db, ob, out);
}